// round 10
// baseline (speedup 1.0000x reference)
#include <cuda_runtime.h>
#include <cuda_bf16.h>
#include <math.h>
#include <cstdint>

typedef unsigned long long ull;

#define T_ 1024
#define B_ 16
#define E_ 1024
#define H_ 512
#define C_ 1024
#define L_ 6
#define M_ (T_*B_)
#define NG 4096
#define KI 1024

// ------------------------ device scratch ------------------------
__device__ float g_xbuf[2][(size_t)M_*C_];       // fp32 activations (layer-3 out / classifier in)
__device__ float g_G[(size_t)M_*NG];             // input-projected gates [m][4096]
__device__ float g_W5[5*E_*C_];                  // conv weights [kk][c] (SIMT conv)
__device__ unsigned short g_Xhi[(size_t)M_*KI];  // bf16 hi plane of activations
__device__ unsigned short g_Xlo[(size_t)M_*KI];  // bf16 lo plane
__device__ unsigned short g_Whi[3][(size_t)NG*KI]; // bf16 hi of wih ([n][k] layout)
__device__ unsigned short g_Wlo[3][(size_t)NG*KI];
__device__ float g_biasG[3][NG];
__device__ float g_bnA[C_], g_bnB[C_];
__device__ float g_h[2][2][H_*B_];
__device__ unsigned g_cnt[2][T_];
__device__ float g_logits[M_*L_];

// ------------------------ helpers ------------------------
__device__ __forceinline__ ull pk2(float x){ ull r; asm("mov.b64 %0,{%1,%1};" : "=l"(r) : "f"(x)); return r; }
__device__ __forceinline__ void fma2(ull& a, ull x, ull y){ asm("fma.rn.f32x2 %0, %1, %2, %0;" : "+l"(a) : "l"(x), "l"(y)); }
__device__ __forceinline__ float2 up2(ull a){ float2 f; asm("mov.b64 {%0,%1}, %2;" : "=f"(f.x), "=f"(f.y) : "l"(a)); return f; }
__device__ __forceinline__ float sigf(float x){ return 1.f/(1.f + expf(-x)); }

__device__ __forceinline__ void split_bf(float v, unsigned short& h, unsigned short& l){
    __nv_bfloat16 hb = __float2bfloat16(v);
    h = __bfloat16_as_ushort(hb);
    l = __bfloat16_as_ushort(__float2bfloat16(v - __bfloat162float(hb)));
}

__device__ __forceinline__ unsigned smem_u32(const void* p){
    unsigned a; asm("{ .reg .u64 t; cvta.to.shared.u64 t, %1; cvt.u32.u64 %0, t; }" : "=r"(a) : "l"(p));
    return a;
}

#define LDSM4(r, a) \
    asm volatile("ldmatrix.sync.aligned.m8n8.x4.shared.b16 {%0,%1,%2,%3}, [%4];" \
        : "=r"((r)[0]),"=r"((r)[1]),"=r"((r)[2]),"=r"((r)[3]) : "r"(a))

#define MMA16816(dd, A, b0, b1) \
    asm volatile("mma.sync.aligned.m16n8k16.row.col.f32.bf16.bf16.f32 " \
        "{%0,%1,%2,%3}, {%4,%5,%6,%7}, {%8,%9}, {%0,%1,%2,%3};" \
        : "+f"((dd)[0]),"+f"((dd)[1]),"+f"((dd)[2]),"+f"((dd)[3]) \
        : "r"((A)[0]),"r"((A)[1]),"r"((A)[2]),"r"((A)[3]), "r"(b0),"r"(b1))

// ------------------------ pack / convert kernels ------------------------
__global__ void k_pack_w5(const float* __restrict__ cw){
    int idx = blockIdx.x*256 + threadIdx.x;
    int c  = idx & (C_-1);
    int kk = idx >> 10;
    int e  = kk & (E_-1);
    int dk = kk >> 10;
    g_W5[idx] = cw[((size_t)c*E_ + e)*5 + dk];
}

__global__ void k_cvt_w(const float* __restrict__ wih){
    size_t idx = (size_t)blockIdx.x*256 + threadIdx.x;   // < 3*4096*1024
    float v = wih[idx];
    unsigned short h, l; split_bf(v, h, l);
    ((unsigned short*)g_Whi)[idx] = h;
    ((unsigned short*)g_Wlo)[idx] = l;
}

__global__ void k_pack_small(const float* __restrict__ bih, const float* __restrict__ bhh,
                             const float* __restrict__ gamma, const float* __restrict__ beta,
                             const float* __restrict__ mean, const float* __restrict__ var,
                             const float* __restrict__ convb){
    int idx = blockIdx.x*256 + threadIdx.x;
    if (idx < 3*NG){
        int l = idx / NG; int n = idx - l*NG;
        int dir = n >> 11, r = n & 2047;
        int src = (l*2+dir)*2048 + r;
        ((float*)g_biasG)[idx] = bih[src] + bhh[src];
    }
    if (idx < C_){
        float s = gamma[idx] * rsqrtf(var[idx] + 1e-5f);
        g_bnA[idx] = s;
        g_bnB[idx] = s*convb[idx] + beta[idx] - mean[idx]*s;
    }
}

__global__ void k_reset(){
    int idx = blockIdx.x*256 + threadIdx.x;
    if (idx < 2*2*H_*B_) ((float*)g_h)[idx] = 0.f;
    if (idx < 2*T_) ((unsigned*)g_cnt)[idx] = 0u;
}

// ------------------------ SIMT conv-as-GEMM + BN + ReLU (bf16 hi/lo output) ------------------------
#define ROWF(i, av) { fma2(acc[i][0],av,b0v.x); fma2(acc[i][1],av,b0v.y); \
                      fma2(acc[i][2],av,b1v.x); fma2(acc[i][3],av,b1v.y); }

__global__ void __launch_bounds__(256,2) k_conv(const float* __restrict__ emb){
    __shared__ float As2[2][8][256];
    __shared__ float Bs[2][8][128];
    int tid = threadIdx.x;
    int m0 = blockIdx.y*128, n0 = blockIdx.x*128;
    int arow = tid>>1, acol = (tid&1)*4;
    int brow = tid>>5, bcol = (tid&31)*4;
    int m = m0 + arow; int t = m>>4, b = m&15;
    const float* Bp = g_W5 + (size_t)brow*C_ + n0 + bcol;

    auto fetchA = [&](int kt)->float4{
        int kk = kt*8 + acol;
        int dk = kk >> 10, e = kk & 1023;
        int tp = t + dk - 2;
        if ((unsigned)tp < 1024u)
            return *(const float4*)(emb + ((size_t)b*1024 + tp)*1024 + e);
        return make_float4(0.f,0.f,0.f,0.f);
    };
    float4 aP = fetchA(0);
    float4 bP = *(const float4*)Bp;
    ull acc[8][4];
    #pragma unroll
    for (int i=0;i<8;i++){ acc[i][0]=0ULL; acc[i][1]=0ULL; acc[i][2]=0ULL; acc[i][3]=0ULL; }
    int tx = tid&15, ty = tid>>4;
    {
        *(ull*)&As2[0][acol+0][2*arow] = pk2(aP.x);
        *(ull*)&As2[0][acol+1][2*arow] = pk2(aP.y);
        *(ull*)&As2[0][acol+2][2*arow] = pk2(aP.z);
        *(ull*)&As2[0][acol+3][2*arow] = pk2(aP.w);
        *(float4*)&Bs[0][brow][bcol] = bP;
    }
    __syncthreads();

    for (int kt=0; kt<640; ++kt){
        int buf = kt & 1;
        if (kt+1 < 640){ aP = fetchA(kt+1); bP = *(const float4*)(Bp + (size_t)(kt+1)*8*C_); }
        #pragma unroll
        for (int k = 0; k < 8; k++){
            ulonglong2 aA = *(const ulonglong2*)&As2[buf][k][ty*8];
            ulonglong2 aB = *(const ulonglong2*)&As2[buf][k][ty*8+4];
            ulonglong2 aC = *(const ulonglong2*)&As2[buf][k][128+ty*8];
            ulonglong2 aD = *(const ulonglong2*)&As2[buf][k][128+ty*8+4];
            ulonglong2 b0v = *(const ulonglong2*)&Bs[buf][k][tx*4];
            ulonglong2 b1v = *(const ulonglong2*)&Bs[buf][k][64+tx*4];
            ROWF(0, aA.x) ROWF(1, aA.y) ROWF(2, aB.x) ROWF(3, aB.y)
            ROWF(4, aC.x) ROWF(5, aC.y) ROWF(6, aD.x) ROWF(7, aD.y)
        }
        if (kt+1 < 640){
            int nb = buf^1;
            *(ull*)&As2[nb][acol+0][2*arow] = pk2(aP.x);
            *(ull*)&As2[nb][acol+1][2*arow] = pk2(aP.y);
            *(ull*)&As2[nb][acol+2][2*arow] = pk2(aP.z);
            *(ull*)&As2[nb][acol+3][2*arow] = pk2(aP.w);
            *(float4*)&Bs[nb][brow][bcol] = bP;
        }
        __syncthreads();
    }
    int c0 = n0 + tx*4;
    float4 A0 = *(const float4*)&g_bnA[c0];    float4 Bb0 = *(const float4*)&g_bnB[c0];
    float4 A1 = *(const float4*)&g_bnA[c0+64]; float4 Bb1 = *(const float4*)&g_bnB[c0+64];
    #pragma unroll
    for (int i=0;i<8;i++){
        int mr = m0 + (i<4 ? ty*4+i : 64+ty*4+(i-4));
        float2 p0=up2(acc[i][0]), p1=up2(acc[i][1]), p2=up2(acc[i][2]), p3=up2(acc[i][3]);
        float v[8];
        v[0]=fmaxf(p0.x*A0.x+Bb0.x,0.f); v[1]=fmaxf(p0.y*A0.y+Bb0.y,0.f);
        v[2]=fmaxf(p1.x*A0.z+Bb0.z,0.f); v[3]=fmaxf(p1.y*A0.w+Bb0.w,0.f);
        v[4]=fmaxf(p2.x*A1.x+Bb1.x,0.f); v[5]=fmaxf(p2.y*A1.y+Bb1.y,0.f);
        v[6]=fmaxf(p3.x*A1.z+Bb1.z,0.f); v[7]=fmaxf(p3.y*A1.w+Bb1.w,0.f);
        ushort4 hi0, lo0, hi1, lo1;
        split_bf(v[0], hi0.x, lo0.x); split_bf(v[1], hi0.y, lo0.y);
        split_bf(v[2], hi0.z, lo0.z); split_bf(v[3], hi0.w, lo0.w);
        split_bf(v[4], hi1.x, lo1.x); split_bf(v[5], hi1.y, lo1.y);
        split_bf(v[6], hi1.z, lo1.z); split_bf(v[7], hi1.w, lo1.w);
        *(ushort4*)&g_Xhi[(size_t)mr*1024 + c0]      = hi0;
        *(ushort4*)&g_Xlo[(size_t)mr*1024 + c0]      = lo0;
        *(ushort4*)&g_Xhi[(size_t)mr*1024 + c0 + 64] = hi1;
        *(ushort4*)&g_Xlo[(size_t)mr*1024 + c0 + 64] = lo1;
    }
}

// ------------------------ mma.sync split-bf16 gate GEMM ------------------------
#define PLANE_B 10240            // 128*80
#define STAGE_B (4*PLANE_B)      // 40960
#define GT_SMEM (2*STAGE_B)      // 81920

__global__ void __launch_bounds__(256) k_gate(int layer){
    extern __shared__ char smem[];
    unsigned sbase = smem_u32(smem);
    int tid = threadIdx.x;
    int wid = tid >> 5, lane = tid & 31;
    int m0 = blockIdx.y*128, n0 = blockIdx.x*128;

    const unsigned short* srcs[4] = {
        g_Xhi + (size_t)m0*1024,
        g_Xlo + (size_t)m0*1024,
        g_Whi[layer] + (size_t)n0*1024,
        g_Wlo[layer] + (size_t)n0*1024
    };

    auto prefetch = [&](int kc, int stg){
        unsigned sb = sbase + stg*STAGE_B;
        #pragma unroll
        for (int it = 0; it < 8; ++it){
            int i = it*256 + tid;              // 0..2047
            int p = i >> 9, rem = i & 511;
            int row = rem >> 2, c = rem & 3;
            unsigned sa = sb + p*PLANE_B + row*80 + c*16;
            const void* ga = srcs[p] + (size_t)row*1024 + kc*32 + c*8;
            asm volatile("cp.async.cg.shared.global [%0], [%1], 16;" :: "r"(sa), "l"(ga) : "memory");
        }
        asm volatile("cp.async.commit_group;" ::: "memory");
    };

    int wm = wid >> 1, wn = wid & 1;
    float d[2][8][4];
    #pragma unroll
    for (int mi=0;mi<2;++mi)
        #pragma unroll
        for (int ni=0;ni<8;++ni)
            #pragma unroll
            for (int q=0;q<4;++q) d[mi][ni][q] = 0.f;

    prefetch(0, 0);

    for (int kt = 0; kt < 32; ++kt){
        int stg = kt & 1;
        asm volatile("cp.async.wait_group 0;" ::: "memory");
        __syncthreads();
        if (kt + 1 < 32) prefetch(kt + 1, stg ^ 1);

        unsigned sb  = sbase + stg*STAGE_B;
        unsigned aHi = sb,            aLo = sb + PLANE_B;
        unsigned bHi = sb + 2*PLANE_B, bLo = sb + 3*PLANE_B;

        #pragma unroll
        for (int kh = 0; kh < 2; ++kh){
            unsigned Ah[2][4], Al[2][4];
            #pragma unroll
            for (int mi = 0; mi < 2; ++mi){
                int row = wm*32 + mi*16 + (lane & 15);
                int ch  = kh*2 + (lane >> 4);
                unsigned off = row*80 + ch*16;
                LDSM4(Ah[mi], aHi + off);
                LDSM4(Al[mi], aLo + off);
            }
            unsigned Bh[4][4], Bl[4][4];
            #pragma unroll
            for (int pr = 0; pr < 4; ++pr){
                int row = wn*64 + pr*16 + (lane & 7) + ((lane >> 4) << 3);
                int ch  = kh*2 + ((lane >> 3) & 1);
                unsigned off = row*80 + ch*16;
                LDSM4(Bh[pr], bHi + off);
                LDSM4(Bl[pr], bLo + off);
            }
            #pragma unroll
            for (int mi = 0; mi < 2; ++mi){
                #pragma unroll
                for (int pr = 0; pr < 4; ++pr){
                    MMA16816(d[mi][2*pr],   Ah[mi], Bh[pr][0], Bh[pr][1]);
                    MMA16816(d[mi][2*pr],   Ah[mi], Bl[pr][0], Bl[pr][1]);
                    MMA16816(d[mi][2*pr],   Al[mi], Bh[pr][0], Bh[pr][1]);
                    MMA16816(d[mi][2*pr+1], Ah[mi], Bh[pr][2], Bh[pr][3]);
                    MMA16816(d[mi][2*pr+1], Ah[mi], Bl[pr][2], Bl[pr][3]);
                    MMA16816(d[mi][2*pr+1], Al[mi], Bh[pr][2], Bh[pr][3]);
                }
            }
        }
    }

    int qr = lane >> 2, qc = lane & 3;
    #pragma unroll
    for (int mi = 0; mi < 2; ++mi){
        #pragma unroll
        for (int ni = 0; ni < 8; ++ni){
            int col = n0 + wn*64 + ni*8 + qc*2;
            float2 bq = *(const float2*)&g_biasG[layer][col];
            int r0 = m0 + wm*32 + mi*16 + qr;
            float2 v0 = make_float2(d[mi][ni][0] + bq.x, d[mi][ni][1] + bq.y);
            *(float2*)&g_G[(size_t)r0*NG + col] = v0;
            float2 v1 = make_float2(d[mi][ni][2] + bq.x, d[mi][ni][3] + bq.y);
            *(float2*)&g_G[(size_t)(r0+8)*NG + col] = v1;
        }
    }
}

// ------------------------ persistent BiLSTM recurrence ------------------------
// Release/acquire barrier (no threadfence); next-layer output stores deferred
// past the release so their drain overlaps the poll. writeF32: fp32 xout
// (layer 3 only, classifier input). writePlanes: bf16 hi/lo (layers 1-2 only,
// next gate GEMM input).
#define SH_STRIDE 516
__global__ void __launch_bounds__(256) k_recur(const float* __restrict__ whh, int layer, int outparity,
                                               int writeF32, int writePlanes){
    extern __shared__ float smemf[];
    float* sW = smemf;
    float* sH = sW + 32*SH_STRIDE;
    float* sG = sH + 16*SH_STRIDE;
    float* sC = sG + 512;
    int tid = threadIdx.x;
    int dir = blockIdx.x >> 6;
    int bid = blockIdx.x & 63;
    int j0 = bid*8;

    for (int i = tid; i < 32*128; i += 256){
        int row = i >> 7, k4 = (i & 127)*4;
        int g = row >> 3, jj = row & 7;
        *(float4*)&sW[row*SH_STRIDE + k4] =
            *(const float4*)&whh[(((size_t)(layer*2+dir))*2048 + g*512 + j0 + jj)*512 + k4];
    }
    if (tid < 128) sC[tid] = 0.f;
    __syncthreads();

    int r  = tid >> 3, bp = tid & 7;
    int b0 = bp, b1 = bp + 8;
    int g  = r >> 3, jj = r & 7;
    int col = dir*2048 + g*512 + j0 + jj;
    float* xout = g_xbuf[outparity];
    unsigned* cnt = &g_cnt[dir][0];

    int t0 = dir ? (T_-1) : 0;
    float gA = g_G[(size_t)(t0*16 + b0)*NG + col];
    float gB = g_G[(size_t)(t0*16 + b1)*NG + col];

    for (int s = 0; s < T_; ++s){
        const float* hin = g_h[dir][s & 1];
        for (int i = tid; i < 2048; i += 256){
            int bb = i >> 7, k4 = (i & 127)*4;
            *(float4*)&sH[bb*SH_STRIDE + k4] = __ldcg((const float4*)&hin[bb*512 + k4]);
        }
        __syncthreads();

        float ngA = 0.f, ngB = 0.f;
        if (s+1 < T_){
            int tn = dir ? (T_-2 - s) : (s+1);
            ngA = g_G[(size_t)(tn*16 + b0)*NG + col];
            ngB = g_G[(size_t)(tn*16 + b1)*NG + col];
        }

        ull aA0=0ULL, aA1=0ULL, aB0=0ULL, aB1=0ULL;
        const float* wv = &sW[r*SH_STRIDE];
        const float* hA = &sH[b0*SH_STRIDE];
        const float* hB = &sH[b1*SH_STRIDE];
        #pragma unroll 8
        for (int k = 0; k < 512; k += 8){
            ulonglong2 wa = *(const ulonglong2*)&wv[k];
            ulonglong2 wb = *(const ulonglong2*)&wv[k+4];
            ulonglong2 xa = *(const ulonglong2*)&hA[k];
            ulonglong2 xb = *(const ulonglong2*)&hA[k+4];
            ulonglong2 ya = *(const ulonglong2*)&hB[k];
            ulonglong2 yb = *(const ulonglong2*)&hB[k+4];
            fma2(aA0, wa.x, xa.x); fma2(aA0, wa.y, xa.y);
            fma2(aA1, wb.x, xb.x); fma2(aA1, wb.y, xb.y);
            fma2(aB0, wa.x, ya.x); fma2(aB0, wa.y, ya.y);
            fma2(aB1, wb.x, yb.x); fma2(aB1, wb.y, yb.y);
        }
        float2 fa0 = up2(aA0), fa1 = up2(aA1), fb0 = up2(aB0), fb1 = up2(aB1);
        sG[r*16 + b0] = gA + (fa0.x + fa0.y) + (fa1.x + fa1.y);
        sG[r*16 + b1] = gB + (fb0.x + fb0.y) + (fb1.x + fb1.y);
        gA = ngA; gB = ngB;
        __syncthreads();

        float hval = 0.f;
        size_t mo = 0;
        if (tid < 128){
            int jj2 = tid >> 4, b2 = tid & 15;
            float gi = sG[(0*8+jj2)*16+b2];
            float gf = sG[(1*8+jj2)*16+b2];
            float gg = sG[(2*8+jj2)*16+b2];
            float go = sG[(3*8+jj2)*16+b2];
            float c = sigf(gf)*sC[jj2*16+b2] + sigf(gi)*tanhf(gg);
            sC[jj2*16+b2] = c;
            hval = sigf(go)*tanhf(c);
            g_h[dir][(s+1)&1][b2*512 + j0 + jj2] = hval;     // the only store in the release chain
            int t2 = dir ? (T_-1 - s) : s;
            mo = (size_t)(t2*16 + b2)*1024 + dir*512 + j0 + jj2;
        }
        __syncthreads();
        if (tid == 0){
            asm volatile("red.release.gpu.global.add.u32 [%0], %1;"
                         :: "l"(&cnt[s]), "r"(1u) : "memory");
        }
        // deferred next-layer output stores — outside the release chain,
        // drain while tid0 polls
        if (tid < 128){
            if (writeF32) xout[mo] = hval;
            if (writePlanes){
                unsigned short hh, hl; split_bf(hval, hh, hl);
                g_Xhi[mo] = hh;
                g_Xlo[mo] = hl;
            }
        }
        if (tid == 0){
            unsigned v;
            do {
                asm volatile("ld.acquire.gpu.global.u32 %0, [%1];"
                             : "=r"(v) : "l"(&cnt[s]) : "memory");
            } while (v < 64u);
        }
        __syncthreads();
    }
}

// ------------------------ classifier ------------------------
__global__ void __launch_bounds__(256) k_cls(const float* __restrict__ cls_w,
                                             const float* __restrict__ cls_b, int parity){
    __shared__ float sW[L_][1024];
    __shared__ float sB[L_];
    int tid = threadIdx.x;
    for (int i = tid; i < L_*1024; i += 256) ((float*)sW)[i] = cls_w[i];
    if (tid < L_) sB[tid] = cls_b[tid];
    __syncthreads();
    int m = blockIdx.x*256 + tid;
    const float* xr = &g_xbuf[parity][(size_t)m*1024];
    float acc[L_];
    #pragma unroll
    for (int l=0;l<L_;l++) acc[l] = sB[l];
    for (int k = 0; k < 1024; k += 4){
        float4 xv = *(const float4*)&xr[k];
        #pragma unroll
        for (int l=0;l<L_;l++){
            float4 wv = *(const float4*)&sW[l][k];
            acc[l] += xv.x*wv.x + xv.y*wv.y + xv.z*wv.z + xv.w*wv.w;
        }
    }
    #pragma unroll
    for (int l=0;l<L_;l++) g_logits[m*L_ + l] = acc[l];
}

// ------------------------ CRF NLL (one block) ------------------------
__global__ void __launch_bounds__(128) k_crf(const int* __restrict__ att, const int* __restrict__ lab,
                                             const float* __restrict__ startv, const float* __restrict__ endv,
                                             const float* __restrict__ trans, float* __restrict__ out){
    __shared__ float sT[36], sS[6], sE[6];
    __shared__ float sAl[16][6];
    __shared__ float sNum[16], sLoss[16];
    int tid = threadIdx.x;
    if (tid < 36) sT[tid] = trans[tid];
    if (tid < 6){ sS[tid] = startv[tid]; sE[tid] = endv[tid]; }
    __syncthreads();

    bool isDen = tid < 96;
    bool isNum = (tid >= 96) && (tid < 112);
    int b = isDen ? tid/6 : tid-96;
    int j = tid % 6;

    float score = 0.f; int prev = 0;
    if (isDen) sAl[b][j] = sS[j] + g_logits[b*L_ + j];
    if (isNum){
        int l0 = lab[b*T_];
        int t0 = (l0 == -100) ? 0 : l0;
        score = sS[t0] + g_logits[b*L_ + t0];
        prev = t0;
    }
    __syncthreads();

    for (int t = 1; t < T_; ++t){
        float nxt = 0.f; bool mk = false;
        if (isDen){
            mk = (att[b*T_ + t] != 0) && (lab[b*T_ + t] != -100);
            float e = g_logits[(t*16 + b)*L_ + j];
            float mx = -1e30f;
            #pragma unroll
            for (int i2=0;i2<6;i2++) mx = fmaxf(mx, sAl[b][i2] + sT[i2*6+j]);
            float ss = 0.f;
            #pragma unroll
            for (int i2=0;i2<6;i2++) ss += expf(sAl[b][i2] + sT[i2*6+j] - mx);
            nxt = mx + logf(ss) + e;
        } else if (isNum){
            int lb = lab[b*T_ + t];
            bool m = (att[b*T_ + t] != 0) && (lb != -100);
            int tt = (lb == -100) ? 0 : lb;
            if (m){
                score += sT[prev*6 + tt] + g_logits[(t*16 + b)*L_ + tt];
                prev = tt;
            }
        }
        __syncthreads();
        if (isDen && mk) sAl[b][j] = nxt;
        __syncthreads();
    }

    if (isNum) sNum[b] = score + sE[prev];
    __syncthreads();
    if (tid < 16){
        float mx = -1e30f;
        #pragma unroll
        for (int jj=0;jj<6;jj++) mx = fmaxf(mx, sAl[tid][jj] + sE[jj]);
        float ss = 0.f;
        #pragma unroll
        for (int jj=0;jj<6;jj++) ss += expf(sAl[tid][jj] + sE[jj] - mx);
        float den = mx + logf(ss);
        sLoss[tid] = den - sNum[tid];
    }
    __syncthreads();
    if (tid == 0){
        float s = 0.f;
        for (int i=0;i<16;i++) s += sLoss[i];
        out[0] = s / 16.f;
    }
}

// ------------------------ launch ------------------------
extern "C" void kernel_launch(void* const* d_in, const int* in_sizes, int n_in,
                              void* d_out, int out_size){
    const float* emb    = (const float*)d_in[0];
    const int*   att    = (const int*)  d_in[1];
    const int*   lab    = (const int*)  d_in[2];
    const float* conv_w = (const float*)d_in[3];
    const float* conv_b = (const float*)d_in[4];
    const float* bn_g   = (const float*)d_in[5];
    const float* bn_b   = (const float*)d_in[6];
    const float* bn_m   = (const float*)d_in[7];
    const float* bn_v   = (const float*)d_in[8];
    const float* wih    = (const float*)d_in[9];
    const float* whh    = (const float*)d_in[10];
    const float* bih    = (const float*)d_in[11];
    const float* bhh    = (const float*)d_in[12];
    const float* cls_w  = (const float*)d_in[13];
    const float* cls_b  = (const float*)d_in[14];
    const float* crf_s  = (const float*)d_in[15];
    const float* crf_e  = (const float*)d_in[16];
    const float* crf_t  = (const float*)d_in[17];
    float* out = (float*)d_out;

    const int RECUR_SMEM = (32*SH_STRIDE + 16*SH_STRIDE + 512 + 128) * 4;
    cudaFuncSetAttribute(k_recur, cudaFuncAttributeMaxDynamicSharedMemorySize, RECUR_SMEM);
    cudaFuncSetAttribute(k_gate,  cudaFuncAttributeMaxDynamicSharedMemorySize, GT_SMEM);

    k_pack_w5   <<<5*E_*C_/256, 256>>>(conv_w);
    k_cvt_w     <<<3*NG*KI/256, 256>>>(wih);
    k_pack_small<<<48, 256>>>(bih, bhh, bn_g, bn_b, bn_m, bn_v, conv_b);

    k_conv<<<dim3(C_/128, M_/128), 256>>>(emb);

    for (int l = 0; l < 3; ++l){
        int outpar = (l + 1) & 1;
        int wF32    = (l == 2) ? 1 : 0;
        int wPlanes = (l == 2) ? 0 : 1;
        k_gate<<<dim3(NG/128, M_/128), 256, GT_SMEM>>>(l);
        k_reset<<<128, 256>>>();
        k_recur<<<128, 256, RECUR_SMEM>>>(whh, l, outpar, wF32, wPlanes);
    }

    k_cls<<<M_/256, 256>>>(cls_w, cls_b, 1);
    k_crf<<<1, 128>>>(att, lab, crf_s, crf_e, crf_t, out);
}

// round 11
// speedup vs baseline: 1.5064x; 1.5064x over previous
#include <cuda_runtime.h>
#include <cuda_bf16.h>
#include <math.h>
#include <cstdint>

typedef unsigned long long ull;

#define T_ 1024
#define B_ 16
#define E_ 1024
#define H_ 512
#define C_ 1024
#define L_ 6
#define M_ (T_*B_)
#define NG 4096
#define KI 1024

// ------------------------ device scratch ------------------------
__device__ float g_xbuf[2][(size_t)M_*C_];       // fp32 activations (layer-3 out / classifier in)
__device__ float g_G[(size_t)M_*NG];             // input-projected gates [m][4096]
__device__ float g_W5[5*E_*C_];                  // conv weights [kk][c] (SIMT conv)
__device__ unsigned short g_Xhi[(size_t)M_*KI];  // bf16 hi plane of activations
__device__ unsigned short g_Xlo[(size_t)M_*KI];  // bf16 lo plane
__device__ unsigned short g_Whi[3][(size_t)NG*KI]; // bf16 hi of wih ([n][k] layout)
__device__ unsigned short g_Wlo[3][(size_t)NG*KI];
__device__ float g_biasG[3][NG];
__device__ float g_bnA[C_], g_bnB[C_];
__device__ unsigned g_hPk[2][2][H_*B_];          // packed h: (bf16hi<<16)|bf16lo, layout [b*512+j]
__device__ unsigned g_cnt[2][T_];
__device__ float g_logits[M_*L_];

// ------------------------ helpers ------------------------
__device__ __forceinline__ ull pk2(float x){ ull r; asm("mov.b64 %0,{%1,%1};" : "=l"(r) : "f"(x)); return r; }
__device__ __forceinline__ void fma2(ull& a, ull x, ull y){ asm("fma.rn.f32x2 %0, %1, %2, %0;" : "+l"(a) : "l"(x), "l"(y)); }
__device__ __forceinline__ float2 up2(ull a){ float2 f; asm("mov.b64 {%0,%1}, %2;" : "=f"(f.x), "=f"(f.y) : "l"(a)); return f; }
__device__ __forceinline__ float sigf(float x){ return 1.f/(1.f + expf(-x)); }

__device__ __forceinline__ void split_bf(float v, unsigned short& h, unsigned short& l){
    __nv_bfloat16 hb = __float2bfloat16(v);
    h = __bfloat16_as_ushort(hb);
    l = __bfloat16_as_ushort(__float2bfloat16(v - __bfloat162float(hb)));
}

__device__ __forceinline__ unsigned smem_u32(const void* p){
    unsigned a; asm("{ .reg .u64 t; cvta.to.shared.u64 t, %1; cvt.u32.u64 %0, t; }" : "=r"(a) : "l"(p));
    return a;
}

#define LDSM4(r, a) \
    asm volatile("ldmatrix.sync.aligned.m8n8.x4.shared.b16 {%0,%1,%2,%3}, [%4];" \
        : "=r"((r)[0]),"=r"((r)[1]),"=r"((r)[2]),"=r"((r)[3]) : "r"(a))

#define MMA16816(dd, A, b0, b1) \
    asm volatile("mma.sync.aligned.m16n8k16.row.col.f32.bf16.bf16.f32 " \
        "{%0,%1,%2,%3}, {%4,%5,%6,%7}, {%8,%9}, {%0,%1,%2,%3};" \
        : "+f"((dd)[0]),"+f"((dd)[1]),"+f"((dd)[2]),"+f"((dd)[3]) \
        : "r"((A)[0]),"r"((A)[1]),"r"((A)[2]),"r"((A)[3]), "r"(b0),"r"(b1))

// ------------------------ pack / convert kernels ------------------------
__global__ void k_pack_w5(const float* __restrict__ cw){
    int idx = blockIdx.x*256 + threadIdx.x;
    int c  = idx & (C_-1);
    int kk = idx >> 10;
    int e  = kk & (E_-1);
    int dk = kk >> 10;
    g_W5[idx] = cw[((size_t)c*E_ + e)*5 + dk];
}

__global__ void k_cvt_w(const float* __restrict__ wih){
    size_t idx = (size_t)blockIdx.x*256 + threadIdx.x;   // < 3*4096*1024
    float v = wih[idx];
    unsigned short h, l; split_bf(v, h, l);
    ((unsigned short*)g_Whi)[idx] = h;
    ((unsigned short*)g_Wlo)[idx] = l;
}

__global__ void k_pack_small(const float* __restrict__ bih, const float* __restrict__ bhh,
                             const float* __restrict__ gamma, const float* __restrict__ beta,
                             const float* __restrict__ mean, const float* __restrict__ var,
                             const float* __restrict__ convb){
    int idx = blockIdx.x*256 + threadIdx.x;
    if (idx < 3*NG){
        int l = idx / NG; int n = idx - l*NG;
        int dir = n >> 11, r = n & 2047;
        int src = (l*2+dir)*2048 + r;
        ((float*)g_biasG)[idx] = bih[src] + bhh[src];
    }
    if (idx < C_){
        float s = gamma[idx] * rsqrtf(var[idx] + 1e-5f);
        g_bnA[idx] = s;
        g_bnB[idx] = s*convb[idx] + beta[idx] - mean[idx]*s;
    }
}

__global__ void k_reset(){
    int idx = blockIdx.x*256 + threadIdx.x;
    if (idx < 2*2*H_*B_) ((unsigned*)g_hPk)[idx] = 0u;
    if (idx < 2*T_) ((unsigned*)g_cnt)[idx] = 0u;
}

// ------------------------ SIMT conv-as-GEMM + BN + ReLU (bf16 hi/lo output) ------------------------
#define ROWF(i, av) { fma2(acc[i][0],av,b0v.x); fma2(acc[i][1],av,b0v.y); \
                      fma2(acc[i][2],av,b1v.x); fma2(acc[i][3],av,b1v.y); }

__global__ void __launch_bounds__(256,2) k_conv(const float* __restrict__ emb){
    __shared__ float As2[2][8][256];
    __shared__ float Bs[2][8][128];
    int tid = threadIdx.x;
    int m0 = blockIdx.y*128, n0 = blockIdx.x*128;
    int arow = tid>>1, acol = (tid&1)*4;
    int brow = tid>>5, bcol = (tid&31)*4;
    int m = m0 + arow; int t = m>>4, b = m&15;
    const float* Bp = g_W5 + (size_t)brow*C_ + n0 + bcol;

    auto fetchA = [&](int kt)->float4{
        int kk = kt*8 + acol;
        int dk = kk >> 10, e = kk & 1023;
        int tp = t + dk - 2;
        if ((unsigned)tp < 1024u)
            return *(const float4*)(emb + ((size_t)b*1024 + tp)*1024 + e);
        return make_float4(0.f,0.f,0.f,0.f);
    };
    float4 aP = fetchA(0);
    float4 bP = *(const float4*)Bp;
    ull acc[8][4];
    #pragma unroll
    for (int i=0;i<8;i++){ acc[i][0]=0ULL; acc[i][1]=0ULL; acc[i][2]=0ULL; acc[i][3]=0ULL; }
    int tx = tid&15, ty = tid>>4;
    {
        *(ull*)&As2[0][acol+0][2*arow] = pk2(aP.x);
        *(ull*)&As2[0][acol+1][2*arow] = pk2(aP.y);
        *(ull*)&As2[0][acol+2][2*arow] = pk2(aP.z);
        *(ull*)&As2[0][acol+3][2*arow] = pk2(aP.w);
        *(float4*)&Bs[0][brow][bcol] = bP;
    }
    __syncthreads();

    for (int kt=0; kt<640; ++kt){
        int buf = kt & 1;
        if (kt+1 < 640){ aP = fetchA(kt+1); bP = *(const float4*)(Bp + (size_t)(kt+1)*8*C_); }
        #pragma unroll
        for (int k = 0; k < 8; k++){
            ulonglong2 aA = *(const ulonglong2*)&As2[buf][k][ty*8];
            ulonglong2 aB = *(const ulonglong2*)&As2[buf][k][ty*8+4];
            ulonglong2 aC = *(const ulonglong2*)&As2[buf][k][128+ty*8];
            ulonglong2 aD = *(const ulonglong2*)&As2[buf][k][128+ty*8+4];
            ulonglong2 b0v = *(const ulonglong2*)&Bs[buf][k][tx*4];
            ulonglong2 b1v = *(const ulonglong2*)&Bs[buf][k][64+tx*4];
            ROWF(0, aA.x) ROWF(1, aA.y) ROWF(2, aB.x) ROWF(3, aB.y)
            ROWF(4, aC.x) ROWF(5, aC.y) ROWF(6, aD.x) ROWF(7, aD.y)
        }
        if (kt+1 < 640){
            int nb = buf^1;
            *(ull*)&As2[nb][acol+0][2*arow] = pk2(aP.x);
            *(ull*)&As2[nb][acol+1][2*arow] = pk2(aP.y);
            *(ull*)&As2[nb][acol+2][2*arow] = pk2(aP.z);
            *(ull*)&As2[nb][acol+3][2*arow] = pk2(aP.w);
            *(float4*)&Bs[nb][brow][bcol] = bP;
        }
        __syncthreads();
    }
    int c0 = n0 + tx*4;
    float4 A0 = *(const float4*)&g_bnA[c0];    float4 Bb0 = *(const float4*)&g_bnB[c0];
    float4 A1 = *(const float4*)&g_bnA[c0+64]; float4 Bb1 = *(const float4*)&g_bnB[c0+64];
    #pragma unroll
    for (int i=0;i<8;i++){
        int mr = m0 + (i<4 ? ty*4+i : 64+ty*4+(i-4));
        float2 p0=up2(acc[i][0]), p1=up2(acc[i][1]), p2=up2(acc[i][2]), p3=up2(acc[i][3]);
        float v[8];
        v[0]=fmaxf(p0.x*A0.x+Bb0.x,0.f); v[1]=fmaxf(p0.y*A0.y+Bb0.y,0.f);
        v[2]=fmaxf(p1.x*A0.z+Bb0.z,0.f); v[3]=fmaxf(p1.y*A0.w+Bb0.w,0.f);
        v[4]=fmaxf(p2.x*A1.x+Bb1.x,0.f); v[5]=fmaxf(p2.y*A1.y+Bb1.y,0.f);
        v[6]=fmaxf(p3.x*A1.z+Bb1.z,0.f); v[7]=fmaxf(p3.y*A1.w+Bb1.w,0.f);
        ushort4 hi0, lo0, hi1, lo1;
        split_bf(v[0], hi0.x, lo0.x); split_bf(v[1], hi0.y, lo0.y);
        split_bf(v[2], hi0.z, lo0.z); split_bf(v[3], hi0.w, lo0.w);
        split_bf(v[4], hi1.x, lo1.x); split_bf(v[5], hi1.y, lo1.y);
        split_bf(v[6], hi1.z, lo1.z); split_bf(v[7], hi1.w, lo1.w);
        *(ushort4*)&g_Xhi[(size_t)mr*1024 + c0]      = hi0;
        *(ushort4*)&g_Xlo[(size_t)mr*1024 + c0]      = lo0;
        *(ushort4*)&g_Xhi[(size_t)mr*1024 + c0 + 64] = hi1;
        *(ushort4*)&g_Xlo[(size_t)mr*1024 + c0 + 64] = lo1;
    }
}

// ------------------------ mma.sync split-bf16 gate GEMM ------------------------
#define PLANE_B 10240            // 128*80
#define STAGE_B (4*PLANE_B)      // 40960
#define GT_SMEM (2*STAGE_B)      // 81920

__global__ void __launch_bounds__(256) k_gate(int layer){
    extern __shared__ char smem[];
    unsigned sbase = smem_u32(smem);
    int tid = threadIdx.x;
    int wid = tid >> 5, lane = tid & 31;
    int m0 = blockIdx.y*128, n0 = blockIdx.x*128;

    const unsigned short* srcs[4] = {
        g_Xhi + (size_t)m0*1024,
        g_Xlo + (size_t)m0*1024,
        g_Whi[layer] + (size_t)n0*1024,
        g_Wlo[layer] + (size_t)n0*1024
    };

    auto prefetch = [&](int kc, int stg){
        unsigned sb = sbase + stg*STAGE_B;
        #pragma unroll
        for (int it = 0; it < 8; ++it){
            int i = it*256 + tid;              // 0..2047
            int p = i >> 9, rem = i & 511;
            int row = rem >> 2, c = rem & 3;
            unsigned sa = sb + p*PLANE_B + row*80 + c*16;
            const void* ga = srcs[p] + (size_t)row*1024 + kc*32 + c*8;
            asm volatile("cp.async.cg.shared.global [%0], [%1], 16;" :: "r"(sa), "l"(ga) : "memory");
        }
        asm volatile("cp.async.commit_group;" ::: "memory");
    };

    int wm = wid >> 1, wn = wid & 1;
    float d[2][8][4];
    #pragma unroll
    for (int mi=0;mi<2;++mi)
        #pragma unroll
        for (int ni=0;ni<8;++ni)
            #pragma unroll
            for (int q=0;q<4;++q) d[mi][ni][q] = 0.f;

    prefetch(0, 0);

    for (int kt = 0; kt < 32; ++kt){
        int stg = kt & 1;
        asm volatile("cp.async.wait_group 0;" ::: "memory");
        __syncthreads();
        if (kt + 1 < 32) prefetch(kt + 1, stg ^ 1);

        unsigned sb  = sbase + stg*STAGE_B;
        unsigned aHi = sb,            aLo = sb + PLANE_B;
        unsigned bHi = sb + 2*PLANE_B, bLo = sb + 3*PLANE_B;

        #pragma unroll
        for (int kh = 0; kh < 2; ++kh){
            unsigned Ah[2][4], Al[2][4];
            #pragma unroll
            for (int mi = 0; mi < 2; ++mi){
                int row = wm*32 + mi*16 + (lane & 15);
                int ch  = kh*2 + (lane >> 4);
                unsigned off = row*80 + ch*16;
                LDSM4(Ah[mi], aHi + off);
                LDSM4(Al[mi], aLo + off);
            }
            unsigned Bh[4][4], Bl[4][4];
            #pragma unroll
            for (int pr = 0; pr < 4; ++pr){
                int row = wn*64 + pr*16 + (lane & 7) + ((lane >> 4) << 3);
                int ch  = kh*2 + ((lane >> 3) & 1);
                unsigned off = row*80 + ch*16;
                LDSM4(Bh[pr], bHi + off);
                LDSM4(Bl[pr], bLo + off);
            }
            #pragma unroll
            for (int mi = 0; mi < 2; ++mi){
                #pragma unroll
                for (int pr = 0; pr < 4; ++pr){
                    MMA16816(d[mi][2*pr],   Ah[mi], Bh[pr][0], Bh[pr][1]);
                    MMA16816(d[mi][2*pr],   Ah[mi], Bl[pr][0], Bl[pr][1]);
                    MMA16816(d[mi][2*pr],   Al[mi], Bh[pr][0], Bh[pr][1]);
                    MMA16816(d[mi][2*pr+1], Ah[mi], Bh[pr][2], Bh[pr][3]);
                    MMA16816(d[mi][2*pr+1], Ah[mi], Bl[pr][2], Bl[pr][3]);
                    MMA16816(d[mi][2*pr+1], Al[mi], Bh[pr][2], Bh[pr][3]);
                }
            }
        }
    }

    int qr = lane >> 2, qc = lane & 3;
    #pragma unroll
    for (int mi = 0; mi < 2; ++mi){
        #pragma unroll
        for (int ni = 0; ni < 8; ++ni){
            int col = n0 + wn*64 + ni*8 + qc*2;
            float2 bq = *(const float2*)&g_biasG[layer][col];
            int r0 = m0 + wm*32 + mi*16 + qr;
            float2 v0 = make_float2(d[mi][ni][0] + bq.x, d[mi][ni][1] + bq.y);
            *(float2*)&g_G[(size_t)r0*NG + col] = v0;
            float2 v1 = make_float2(d[mi][ni][2] + bq.x, d[mi][ni][3] + bq.y);
            *(float2*)&g_G[(size_t)(r0+8)*NG + col] = v1;
        }
    }
}

// ------------------------ persistent BiLSTM recurrence (tensor-core) ------------------------
// 128 blocks: [0,64)=fw, [64,128)=bw; 256 threads (8 warps). Block owns 32 gate
// rows {g*512 + j0+jj : g<4, jj<8}, j0 = bid*8. Whh bf16 hi/lo fragments live in
// REGISTERS (loaded once). Per step: h (packed bf16 hi|lo u32, [b][j] global
// layout) -> smem planes -> ldmatrix -> 3-term split-bf16 MMA (m16=batch,
// n=32 rows, K=512 split across 4 kw warp groups) -> smem partial reduce ->
// cell update -> packed h store -> release/acquire barrier.
// smem: wHi 33280 | wLo 33280 | pHi 16640 | pLo 16640 | sGp 8192 | sC 512
#define RC_WHI   0
#define RC_WLO   33280
#define RC_PHI   66560
#define RC_PLO   83200
#define RC_GP    99840
#define RC_C     108032
#define RC_SMEM  108544

__global__ void __launch_bounds__(256) k_recur(const float* __restrict__ whh, int layer, int outparity,
                                               int writeF32, int writePlanes){
    extern __shared__ char smem[];
    unsigned sb = smem_u32(smem);
    float* sGp = (float*)(smem + RC_GP);
    float* sC  = (float*)(smem + RC_C);
    int tid = threadIdx.x;
    int wid = tid >> 5, lane = tid & 31;
    int nw = wid & 1, kw = wid >> 1;     // nw: 16-row group, kw: K=128 slice
    int dir = blockIdx.x >> 6;
    int bid = blockIdx.x & 63;
    int j0 = bid*8;

    // ---- stage Whh -> bf16 hi/lo smem planes ----
    for (int i = tid; i < 4096; i += 256){          // 4096 float4 = 32 rows x 512
        int row = i >> 7;
        int k4  = (i & 127) * 4;
        int g = row >> 3, jj = row & 7;
        float4 w = *(const float4*)&whh[(((size_t)(layer*2+dir))*2048 + g*512 + j0 + jj)*512 + k4];
        unsigned short h0,l0,h1,l1,h2,l2,h3,l3;
        split_bf(w.x,h0,l0); split_bf(w.y,h1,l1); split_bf(w.z,h2,l2); split_bf(w.w,h3,l3);
        *(uint2*)(smem + RC_WHI + row*1040 + k4*2) =
            make_uint2((unsigned)h0 | ((unsigned)h1<<16), (unsigned)h2 | ((unsigned)h3<<16));
        *(uint2*)(smem + RC_WLO + row*1040 + k4*2) =
            make_uint2((unsigned)l0 | ((unsigned)l1<<16), (unsigned)l2 | ((unsigned)l3<<16));
    }
    if (tid < 128) sC[tid] = 0.f;
    __syncthreads();

    // ---- preload B fragments into registers (static across all steps) ----
    unsigned Bh[8][4], Bl[8][4];
    {
        int rowB = nw*16 + (lane & 7) + ((lane >> 4) << 3);
        int chB  = ((lane >> 3) & 1);
        #pragma unroll
        for (int kt = 0; kt < 8; ++kt){
            int ktile = kw*8 + kt;
            unsigned off = rowB*1040 + ktile*32 + chB*16;
            LDSM4(Bh[kt], sb + RC_WHI + off);
            LDSM4(Bl[kt], sb + RC_WLO + off);
        }
    }
    __syncthreads();

    // ---- cell-thread state ----
    int b2c = tid & 15, jj2c = tid >> 4;            // valid for tid<128
    int colc = dir*2048 + j0 + jj2c;
    float gReg[4] = {0.f,0.f,0.f,0.f};
    if (tid < 128){
        int t0 = dir ? (T_-1) : 0;
        #pragma unroll
        for (int g2 = 0; g2 < 4; ++g2)
            gReg[g2] = g_G[(size_t)(t0*16 + b2c)*NG + colc + g2*512];
    }

    float* xout = g_xbuf[outparity];
    unsigned* cnt = &g_cnt[dir][0];
    int offA_row = (lane & 15)*1040 + (lane >> 4)*16;

    for (int s = 0; s < T_; ++s){
        // stage packed h -> bf16 planes
        const unsigned* hin = g_hPk[dir][s & 1];
        #pragma unroll
        for (int it = 0; it < 8; ++it){
            int i = it*256 + tid;                    // 0..2047
            int b = i >> 7, jq = (i & 127) * 4;
            uint4 v = __ldcg((const uint4*)&hin[b*512 + jq]);
            unsigned hiAB = __byte_perm(v.x, v.y, 0x7632);
            unsigned hiCD = __byte_perm(v.z, v.w, 0x7632);
            unsigned loAB = __byte_perm(v.x, v.y, 0x5410);
            unsigned loCD = __byte_perm(v.z, v.w, 0x5410);
            *(uint2*)(smem + RC_PHI + b*1040 + jq*2) = make_uint2(hiAB, hiCD);
            *(uint2*)(smem + RC_PLO + b*1040 + jq*2) = make_uint2(loAB, loCD);
        }
        __syncthreads();

        // MMA: D[b][row] = sum_k h[b][k] * Whh[row][k]  (3-term split)
        float d0[4] = {0.f,0.f,0.f,0.f}, d1[4] = {0.f,0.f,0.f,0.f};
        #pragma unroll
        for (int kt = 0; kt < 8; ++kt){
            int ktile = kw*8 + kt;
            unsigned offA = offA_row + ktile*32;
            unsigned Ah[4], Al[4];
            LDSM4(Ah, sb + RC_PHI + offA);
            LDSM4(Al, sb + RC_PLO + offA);
            MMA16816(d0, Ah, Bh[kt][0], Bh[kt][1]);
            MMA16816(d0, Ah, Bl[kt][0], Bl[kt][1]);
            MMA16816(d0, Al, Bh[kt][0], Bh[kt][1]);
            MMA16816(d1, Ah, Bh[kt][2], Bh[kt][3]);
            MMA16816(d1, Ah, Bl[kt][2], Bl[kt][3]);
            MMA16816(d1, Al, Bh[kt][2], Bh[kt][3]);
        }
        {
            int qr = lane >> 2, qc = lane & 3;
            int row0 = nw*16 + qc*2, row1 = nw*16 + 8 + qc*2;
            *(float2*)&sGp[(kw*16+qr)*32 + row0]   = make_float2(d0[0], d0[1]);
            *(float2*)&sGp[(kw*16+qr+8)*32 + row0] = make_float2(d0[2], d0[3]);
            *(float2*)&sGp[(kw*16+qr)*32 + row1]   = make_float2(d1[0], d1[1]);
            *(float2*)&sGp[(kw*16+qr+8)*32 + row1] = make_float2(d1[2], d1[3]);
        }
        __syncthreads();

        // cell update (tid<128)
        float hval = 0.f; size_t mo = 0; unsigned hh = 0, hl = 0;
        if (tid < 128){
            float ng[4] = {0.f,0.f,0.f,0.f};
            if (s+1 < T_){
                int tn = dir ? (T_-2 - s) : (s+1);
                #pragma unroll
                for (int g2 = 0; g2 < 4; ++g2)
                    ng[g2] = g_G[(size_t)(tn*16 + b2c)*NG + colc + g2*512];
            }
            float acc4[4];
            #pragma unroll
            for (int g2 = 0; g2 < 4; ++g2){
                int row = g2*8 + jj2c;
                float sd = sGp[(0*16 + b2c)*32 + row] + sGp[(1*16 + b2c)*32 + row]
                         + sGp[(2*16 + b2c)*32 + row] + sGp[(3*16 + b2c)*32 + row];
                acc4[g2] = gReg[g2] + sd;
            }
            float c = sigf(acc4[1])*sC[tid] + sigf(acc4[0])*tanhf(acc4[2]);
            sC[tid] = c;
            hval = sigf(acc4[3])*tanhf(c);
            __nv_bfloat16 hb = __float2bfloat16(hval);
            hh = __bfloat16_as_ushort(hb);
            hl = __bfloat16_as_ushort(__float2bfloat16(hval - __bfloat162float(hb)));
            g_hPk[dir][(s+1)&1][b2c*512 + j0 + jj2c] = (hh << 16) | hl;
            int t2 = dir ? (T_-1 - s) : s;
            mo = (size_t)(t2*16 + b2c)*1024 + dir*512 + j0 + jj2c;
            gReg[0] = ng[0]; gReg[1] = ng[1]; gReg[2] = ng[2]; gReg[3] = ng[3];
        }
        __syncthreads();
        if (tid == 0){
            asm volatile("red.release.gpu.global.add.u32 [%0], %1;"
                         :: "l"(&cnt[s]), "r"(1u) : "memory");
        }
        // deferred next-layer output stores (outside the release chain)
        if (tid < 128){
            if (writeF32) xout[mo] = hval;
            if (writePlanes){
                g_Xhi[mo] = (unsigned short)hh;
                g_Xlo[mo] = (unsigned short)hl;
            }
        }
        if (tid == 0){
            unsigned v;
            do {
                asm volatile("ld.acquire.gpu.global.u32 %0, [%1];"
                             : "=r"(v) : "l"(&cnt[s]) : "memory");
            } while (v < 64u);
        }
        __syncthreads();
    }
}

// ------------------------ classifier ------------------------
__global__ void __launch_bounds__(256) k_cls(const float* __restrict__ cls_w,
                                             const float* __restrict__ cls_b, int parity){
    __shared__ float sW[L_][1024];
    __shared__ float sB[L_];
    int tid = threadIdx.x;
    for (int i = tid; i < L_*1024; i += 256) ((float*)sW)[i] = cls_w[i];
    if (tid < L_) sB[tid] = cls_b[tid];
    __syncthreads();
    int m = blockIdx.x*256 + tid;
    const float* xr = &g_xbuf[parity][(size_t)m*1024];
    float acc[L_];
    #pragma unroll
    for (int l=0;l<L_;l++) acc[l] = sB[l];
    for (int k = 0; k < 1024; k += 4){
        float4 xv = *(const float4*)&xr[k];
        #pragma unroll
        for (int l=0;l<L_;l++){
            float4 wv = *(const float4*)&sW[l][k];
            acc[l] += xv.x*wv.x + xv.y*wv.y + xv.z*wv.z + xv.w*wv.w;
        }
    }
    #pragma unroll
    for (int l=0;l<L_;l++) g_logits[m*L_ + l] = acc[l];
}

// ------------------------ CRF NLL (one block) ------------------------
__global__ void __launch_bounds__(128) k_crf(const int* __restrict__ att, const int* __restrict__ lab,
                                             const float* __restrict__ startv, const float* __restrict__ endv,
                                             const float* __restrict__ trans, float* __restrict__ out){
    __shared__ float sT[36], sS[6], sE[6];
    __shared__ float sAl[16][6];
    __shared__ float sNum[16], sLoss[16];
    int tid = threadIdx.x;
    if (tid < 36) sT[tid] = trans[tid];
    if (tid < 6){ sS[tid] = startv[tid]; sE[tid] = endv[tid]; }
    __syncthreads();

    bool isDen = tid < 96;
    bool isNum = (tid >= 96) && (tid < 112);
    int b = isDen ? tid/6 : tid-96;
    int j = tid % 6;

    float score = 0.f; int prev = 0;
    if (isDen) sAl[b][j] = sS[j] + g_logits[b*L_ + j];
    if (isNum){
        int l0 = lab[b*T_];
        int t0 = (l0 == -100) ? 0 : l0;
        score = sS[t0] + g_logits[b*L_ + t0];
        prev = t0;
    }
    __syncthreads();

    for (int t = 1; t < T_; ++t){
        float nxt = 0.f; bool mk = false;
        if (isDen){
            mk = (att[b*T_ + t] != 0) && (lab[b*T_ + t] != -100);
            float e = g_logits[(t*16 + b)*L_ + j];
            float mx = -1e30f;
            #pragma unroll
            for (int i2=0;i2<6;i2++) mx = fmaxf(mx, sAl[b][i2] + sT[i2*6+j]);
            float ss = 0.f;
            #pragma unroll
            for (int i2=0;i2<6;i2++) ss += expf(sAl[b][i2] + sT[i2*6+j] - mx);
            nxt = mx + logf(ss) + e;
        } else if (isNum){
            int lb = lab[b*T_ + t];
            bool m = (att[b*T_ + t] != 0) && (lb != -100);
            int tt = (lb == -100) ? 0 : lb;
            if (m){
                score += sT[prev*6 + tt] + g_logits[(t*16 + b)*L_ + tt];
                prev = tt;
            }
        }
        __syncthreads();
        if (isDen && mk) sAl[b][j] = nxt;
        __syncthreads();
    }

    if (isNum) sNum[b] = score + sE[prev];
    __syncthreads();
    if (tid < 16){
        float mx = -1e30f;
        #pragma unroll
        for (int jj=0;jj<6;jj++) mx = fmaxf(mx, sAl[tid][jj] + sE[jj]);
        float ss = 0.f;
        #pragma unroll
        for (int jj=0;jj<6;jj++) ss += expf(sAl[tid][jj] + sE[jj] - mx);
        float den = mx + logf(ss);
        sLoss[tid] = den - sNum[tid];
    }
    __syncthreads();
    if (tid == 0){
        float s = 0.f;
        for (int i=0;i<16;i++) s += sLoss[i];
        out[0] = s / 16.f;
    }
}

// ------------------------ launch ------------------------
extern "C" void kernel_launch(void* const* d_in, const int* in_sizes, int n_in,
                              void* d_out, int out_size){
    const float* emb    = (const float*)d_in[0];
    const int*   att    = (const int*)  d_in[1];
    const int*   lab    = (const int*)  d_in[2];
    const float* conv_w = (const float*)d_in[3];
    const float* conv_b = (const float*)d_in[4];
    const float* bn_g   = (const float*)d_in[5];
    const float* bn_b   = (const float*)d_in[6];
    const float* bn_m   = (const float*)d_in[7];
    const float* bn_v   = (const float*)d_in[8];
    const float* wih    = (const float*)d_in[9];
    const float* whh    = (const float*)d_in[10];
    const float* bih    = (const float*)d_in[11];
    const float* bhh    = (const float*)d_in[12];
    const float* cls_w  = (const float*)d_in[13];
    const float* cls_b  = (const float*)d_in[14];
    const float* crf_s  = (const float*)d_in[15];
    const float* crf_e  = (const float*)d_in[16];
    const float* crf_t  = (const float*)d_in[17];
    float* out = (float*)d_out;

    cudaFuncSetAttribute(k_recur, cudaFuncAttributeMaxDynamicSharedMemorySize, RC_SMEM);
    cudaFuncSetAttribute(k_gate,  cudaFuncAttributeMaxDynamicSharedMemorySize, GT_SMEM);

    k_pack_w5   <<<5*E_*C_/256, 256>>>(conv_w);
    k_cvt_w     <<<3*NG*KI/256, 256>>>(wih);
    k_pack_small<<<48, 256>>>(bih, bhh, bn_g, bn_b, bn_m, bn_v, conv_b);

    k_conv<<<dim3(C_/128, M_/128), 256>>>(emb);

    for (int l = 0; l < 3; ++l){
        int outpar = (l + 1) & 1;
        int wF32    = (l == 2) ? 1 : 0;
        int wPlanes = (l == 2) ? 0 : 1;
        k_gate<<<dim3(NG/128, M_/128), 256, GT_SMEM>>>(l);
        k_reset<<<128, 256>>>();
        k_recur<<<128, 256, RC_SMEM>>>(whh, l, outpar, wF32, wPlanes);
    }

    k_cls<<<M_/256, 256>>>(cls_w, cls_b, 1);
    k_crf<<<1, 128>>>(att, lab, crf_s, crf_e, crf_t, out);
}

// round 12
// speedup vs baseline: 1.7958x; 1.1921x over previous
#include <cuda_runtime.h>
#include <cuda_bf16.h>
#include <math.h>
#include <cstdint>

typedef unsigned long long ull;

#define T_ 1024
#define B_ 16
#define E_ 1024
#define H_ 512
#define C_ 1024
#define L_ 6
#define M_ (T_*B_)
#define NG 4096
#define KI 1024
#define KC_ (5*E_)              // 5120 conv GEMM K

// ------------------------ device scratch ------------------------
__device__ float g_xbuf[2][(size_t)M_*C_];       // fp32 activations (layer-3 out / classifier in)
__device__ float g_G[(size_t)M_*NG];             // input-projected gates [m][4096]
__device__ unsigned short g_Xhi[(size_t)M_*KI];  // bf16 hi plane of activations
__device__ unsigned short g_Xlo[(size_t)M_*KI];  // bf16 lo plane
__device__ unsigned short g_Whi[3][(size_t)NG*KI]; // bf16 hi of wih ([n][k] layout)
__device__ unsigned short g_Wlo[3][(size_t)NG*KI];
__device__ unsigned short g_Ehi[(size_t)B_*T_*E_]; // bf16 hi of embeddings
__device__ unsigned short g_Elo[(size_t)B_*T_*E_];
__device__ unsigned short g_CWhi[(size_t)C_*KC_];  // conv w planes, [c][dk*1024+e]
__device__ unsigned short g_CWlo[(size_t)C_*KC_];
__device__ float g_biasG[3][NG];
__device__ float g_bnA[C_], g_bnB[C_];
__device__ unsigned g_hPk[2][2][H_*B_];          // packed h: (bf16hi<<16)|bf16lo, [b*512+j]
__device__ unsigned g_cnt[2][T_];
__device__ float g_logits[M_*L_];

// ------------------------ helpers ------------------------
__device__ __forceinline__ float sigf(float x){ return 1.f/(1.f + expf(-x)); }

__device__ __forceinline__ void split_bf(float v, unsigned short& h, unsigned short& l){
    __nv_bfloat16 hb = __float2bfloat16(v);
    h = __bfloat16_as_ushort(hb);
    l = __bfloat16_as_ushort(__float2bfloat16(v - __bfloat162float(hb)));
}

__device__ __forceinline__ unsigned smem_u32(const void* p){
    unsigned a; asm("{ .reg .u64 t; cvta.to.shared.u64 t, %1; cvt.u32.u64 %0, t; }" : "=r"(a) : "l"(p));
    return a;
}

#define LDSM4(r, a) \
    asm volatile("ldmatrix.sync.aligned.m8n8.x4.shared.b16 {%0,%1,%2,%3}, [%4];" \
        : "=r"((r)[0]),"=r"((r)[1]),"=r"((r)[2]),"=r"((r)[3]) : "r"(a))

#define MMA16816(dd, A, b0, b1) \
    asm volatile("mma.sync.aligned.m16n8k16.row.col.f32.bf16.bf16.f32 " \
        "{%0,%1,%2,%3}, {%4,%5,%6,%7}, {%8,%9}, {%0,%1,%2,%3};" \
        : "+f"((dd)[0]),"+f"((dd)[1]),"+f"((dd)[2]),"+f"((dd)[3]) \
        : "r"((A)[0]),"r"((A)[1]),"r"((A)[2]),"r"((A)[3]), "r"(b0),"r"(b1))

// ------------------------ pack / convert kernels ------------------------
__global__ void k_cvt_e(const float* __restrict__ emb){
    size_t idx = (size_t)blockIdx.x*256 + threadIdx.x;   // < 16*1024*1024
    float v = emb[idx];
    unsigned short h, l; split_bf(v, h, l);
    g_Ehi[idx] = h;
    g_Elo[idx] = l;
}

__global__ void k_cvt_cw(const float* __restrict__ cw){
    size_t idx = (size_t)blockIdx.x*256 + threadIdx.x;   // < 1024*5120
    int c  = (int)(idx / KC_);
    int kk = (int)(idx - (size_t)c*KC_);
    int dk = kk >> 10, e = kk & 1023;
    float v = cw[((size_t)c*E_ + e)*5 + dk];
    unsigned short h, l; split_bf(v, h, l);
    g_CWhi[idx] = h;
    g_CWlo[idx] = l;
}

__global__ void k_cvt_w(const float* __restrict__ wih){
    size_t idx = (size_t)blockIdx.x*256 + threadIdx.x;   // < 3*4096*1024
    float v = wih[idx];
    unsigned short h, l; split_bf(v, h, l);
    ((unsigned short*)g_Whi)[idx] = h;
    ((unsigned short*)g_Wlo)[idx] = l;
}

__global__ void k_pack_small(const float* __restrict__ bih, const float* __restrict__ bhh,
                             const float* __restrict__ gamma, const float* __restrict__ beta,
                             const float* __restrict__ mean, const float* __restrict__ var,
                             const float* __restrict__ convb){
    int idx = blockIdx.x*256 + threadIdx.x;
    if (idx < 3*NG){
        int l = idx / NG; int n = idx - l*NG;
        int dir = n >> 11, r = n & 2047;
        int src = (l*2+dir)*2048 + r;
        ((float*)g_biasG)[idx] = bih[src] + bhh[src];
    }
    if (idx < C_){
        float s = gamma[idx] * rsqrtf(var[idx] + 1e-5f);
        g_bnA[idx] = s;
        g_bnB[idx] = s*convb[idx] + beta[idx] - mean[idx]*s;
    }
}

__global__ void k_reset(){
    int idx = blockIdx.x*256 + threadIdx.x;
    if (idx < 2*2*H_*B_) ((unsigned*)g_hPk)[idx] = 0u;
    if (idx < 2*T_) ((unsigned*)g_cnt)[idx] = 0u;
}

// ------------------------ shared HMMA tile layout ------------------------
#define PLANE_B 10240            // 128*80
#define STAGE_B (4*PLANE_B)      // 40960
#define GT_SMEM (2*STAGE_B)      // 81920

// ------------------------ split-bf16 HMMA conv GEMM + BN + ReLU ------------------------
// X[m][c] = relu(bnA[c]*(sum_kk E[b,t+dk-2,e]*CW[c,kk]) + bnB[c]) -> bf16 hi/lo planes
__global__ void __launch_bounds__(256) k_convT(){
    extern __shared__ char smem[];
    unsigned sbase = smem_u32(smem);
    int tid = threadIdx.x;
    int wid = tid >> 5, lane = tid & 31;
    int m0 = blockIdx.y*128, n0 = blockIdx.x*128;

    auto prefetch = [&](int kc, int stg){
        unsigned sb = sbase + stg*STAGE_B;
        int dk = (kc*32) >> 10;
        int e_base = (kc*32) & 1023;
        #pragma unroll
        for (int it = 0; it < 8; ++it){
            int i = it*256 + tid;              // 0..2047
            int p = i >> 9, rem = i & 511;
            int row = rem >> 2, c = rem & 3;
            unsigned sa = sb + p*PLANE_B + row*80 + c*16;
            if (p < 2){
                int m = m0 + row;
                int t = m >> 4, b = m & 15;
                int tp = t + dk - 2;
                const unsigned short* base = (p == 0) ? g_Ehi : g_Elo;
                const void* ga = base + ((size_t)b*1024 + tp)*1024 + e_base + c*8;
                unsigned sz = ((unsigned)tp < 1024u) ? 16u : 0u;
                asm volatile("cp.async.cg.shared.global [%0], [%1], 16, %2;"
                             :: "r"(sa), "l"(ga), "r"(sz) : "memory");
            } else {
                const unsigned short* base = (p == 2) ? g_CWhi : g_CWlo;
                const void* ga = base + (size_t)(n0 + row)*KC_ + kc*32 + c*8;
                asm volatile("cp.async.cg.shared.global [%0], [%1], 16;"
                             :: "r"(sa), "l"(ga) : "memory");
            }
        }
        asm volatile("cp.async.commit_group;" ::: "memory");
    };

    int wm = wid >> 1, wn = wid & 1;
    float d[2][8][4];
    #pragma unroll
    for (int mi=0;mi<2;++mi)
        #pragma unroll
        for (int ni=0;ni<8;++ni)
            #pragma unroll
            for (int q=0;q<4;++q) d[mi][ni][q] = 0.f;

    prefetch(0, 0);

    for (int kt = 0; kt < KC_/32; ++kt){   // 160
        int stg = kt & 1;
        asm volatile("cp.async.wait_group 0;" ::: "memory");
        __syncthreads();
        if (kt + 1 < KC_/32) prefetch(kt + 1, stg ^ 1);

        unsigned sb  = sbase + stg*STAGE_B;
        unsigned aHi = sb,            aLo = sb + PLANE_B;
        unsigned bHi = sb + 2*PLANE_B, bLo = sb + 3*PLANE_B;

        #pragma unroll
        for (int kh = 0; kh < 2; ++kh){
            unsigned Ah[2][4], Al[2][4];
            #pragma unroll
            for (int mi = 0; mi < 2; ++mi){
                int row = wm*32 + mi*16 + (lane & 15);
                int ch  = kh*2 + (lane >> 4);
                unsigned off = row*80 + ch*16;
                LDSM4(Ah[mi], aHi + off);
                LDSM4(Al[mi], aLo + off);
            }
            unsigned Bh[4][4], Bl[4][4];
            #pragma unroll
            for (int pr = 0; pr < 4; ++pr){
                int row = wn*64 + pr*16 + (lane & 7) + ((lane >> 4) << 3);
                int ch  = kh*2 + ((lane >> 3) & 1);
                unsigned off = row*80 + ch*16;
                LDSM4(Bh[pr], bHi + off);
                LDSM4(Bl[pr], bLo + off);
            }
            #pragma unroll
            for (int mi = 0; mi < 2; ++mi){
                #pragma unroll
                for (int pr = 0; pr < 4; ++pr){
                    MMA16816(d[mi][2*pr],   Ah[mi], Bh[pr][0], Bh[pr][1]);
                    MMA16816(d[mi][2*pr],   Ah[mi], Bl[pr][0], Bl[pr][1]);
                    MMA16816(d[mi][2*pr],   Al[mi], Bh[pr][0], Bh[pr][1]);
                    MMA16816(d[mi][2*pr+1], Ah[mi], Bh[pr][2], Bh[pr][3]);
                    MMA16816(d[mi][2*pr+1], Ah[mi], Bl[pr][2], Bl[pr][3]);
                    MMA16816(d[mi][2*pr+1], Al[mi], Bh[pr][2], Bh[pr][3]);
                }
            }
        }
    }

    // epilogue: BN + ReLU + split-bf16 -> g_Xhi/g_Xlo
    int qr = lane >> 2, qc = lane & 3;
    #pragma unroll
    for (int mi = 0; mi < 2; ++mi){
        #pragma unroll
        for (int ni = 0; ni < 8; ++ni){
            int col = n0 + wn*64 + ni*8 + qc*2;
            float2 A = *(const float2*)&g_bnA[col];
            float2 Bb = *(const float2*)&g_bnB[col];
            int r0 = m0 + wm*32 + mi*16 + qr;
            float v00 = fmaxf(d[mi][ni][0]*A.x + Bb.x, 0.f);
            float v01 = fmaxf(d[mi][ni][1]*A.y + Bb.y, 0.f);
            float v10 = fmaxf(d[mi][ni][2]*A.x + Bb.x, 0.f);
            float v11 = fmaxf(d[mi][ni][3]*A.y + Bb.y, 0.f);
            ushort2 h0, l0, h1, l1;
            split_bf(v00, h0.x, l0.x); split_bf(v01, h0.y, l0.y);
            split_bf(v10, h1.x, l1.x); split_bf(v11, h1.y, l1.y);
            *(ushort2*)&g_Xhi[(size_t)r0*1024 + col]     = h0;
            *(ushort2*)&g_Xlo[(size_t)r0*1024 + col]     = l0;
            *(ushort2*)&g_Xhi[(size_t)(r0+8)*1024 + col] = h1;
            *(ushort2*)&g_Xlo[(size_t)(r0+8)*1024 + col] = l1;
        }
    }
}

// ------------------------ mma.sync split-bf16 gate GEMM ------------------------
__global__ void __launch_bounds__(256) k_gate(int layer){
    extern __shared__ char smem[];
    unsigned sbase = smem_u32(smem);
    int tid = threadIdx.x;
    int wid = tid >> 5, lane = tid & 31;
    int m0 = blockIdx.y*128, n0 = blockIdx.x*128;

    const unsigned short* srcs[4] = {
        g_Xhi + (size_t)m0*1024,
        g_Xlo + (size_t)m0*1024,
        g_Whi[layer] + (size_t)n0*1024,
        g_Wlo[layer] + (size_t)n0*1024
    };

    auto prefetch = [&](int kc, int stg){
        unsigned sb = sbase + stg*STAGE_B;
        #pragma unroll
        for (int it = 0; it < 8; ++it){
            int i = it*256 + tid;              // 0..2047
            int p = i >> 9, rem = i & 511;
            int row = rem >> 2, c = rem & 3;
            unsigned sa = sb + p*PLANE_B + row*80 + c*16;
            const void* ga = srcs[p] + (size_t)row*1024 + kc*32 + c*8;
            asm volatile("cp.async.cg.shared.global [%0], [%1], 16;" :: "r"(sa), "l"(ga) : "memory");
        }
        asm volatile("cp.async.commit_group;" ::: "memory");
    };

    int wm = wid >> 1, wn = wid & 1;
    float d[2][8][4];
    #pragma unroll
    for (int mi=0;mi<2;++mi)
        #pragma unroll
        for (int ni=0;ni<8;++ni)
            #pragma unroll
            for (int q=0;q<4;++q) d[mi][ni][q] = 0.f;

    prefetch(0, 0);

    for (int kt = 0; kt < 32; ++kt){
        int stg = kt & 1;
        asm volatile("cp.async.wait_group 0;" ::: "memory");
        __syncthreads();
        if (kt + 1 < 32) prefetch(kt + 1, stg ^ 1);

        unsigned sb  = sbase + stg*STAGE_B;
        unsigned aHi = sb,            aLo = sb + PLANE_B;
        unsigned bHi = sb + 2*PLANE_B, bLo = sb + 3*PLANE_B;

        #pragma unroll
        for (int kh = 0; kh < 2; ++kh){
            unsigned Ah[2][4], Al[2][4];
            #pragma unroll
            for (int mi = 0; mi < 2; ++mi){
                int row = wm*32 + mi*16 + (lane & 15);
                int ch  = kh*2 + (lane >> 4);
                unsigned off = row*80 + ch*16;
                LDSM4(Ah[mi], aHi + off);
                LDSM4(Al[mi], aLo + off);
            }
            unsigned Bh[4][4], Bl[4][4];
            #pragma unroll
            for (int pr = 0; pr < 4; ++pr){
                int row = wn*64 + pr*16 + (lane & 7) + ((lane >> 4) << 3);
                int ch  = kh*2 + ((lane >> 3) & 1);
                unsigned off = row*80 + ch*16;
                LDSM4(Bh[pr], bHi + off);
                LDSM4(Bl[pr], bLo + off);
            }
            #pragma unroll
            for (int mi = 0; mi < 2; ++mi){
                #pragma unroll
                for (int pr = 0; pr < 4; ++pr){
                    MMA16816(d[mi][2*pr],   Ah[mi], Bh[pr][0], Bh[pr][1]);
                    MMA16816(d[mi][2*pr],   Ah[mi], Bl[pr][0], Bl[pr][1]);
                    MMA16816(d[mi][2*pr],   Al[mi], Bh[pr][0], Bh[pr][1]);
                    MMA16816(d[mi][2*pr+1], Ah[mi], Bh[pr][2], Bh[pr][3]);
                    MMA16816(d[mi][2*pr+1], Ah[mi], Bl[pr][2], Bl[pr][3]);
                    MMA16816(d[mi][2*pr+1], Al[mi], Bh[pr][2], Bh[pr][3]);
                }
            }
        }
    }

    int qr = lane >> 2, qc = lane & 3;
    #pragma unroll
    for (int mi = 0; mi < 2; ++mi){
        #pragma unroll
        for (int ni = 0; ni < 8; ++ni){
            int col = n0 + wn*64 + ni*8 + qc*2;
            float2 bq = *(const float2*)&g_biasG[layer][col];
            int r0 = m0 + wm*32 + mi*16 + qr;
            float2 v0 = make_float2(d[mi][ni][0] + bq.x, d[mi][ni][1] + bq.y);
            *(float2*)&g_G[(size_t)r0*NG + col] = v0;
            float2 v1 = make_float2(d[mi][ni][2] + bq.x, d[mi][ni][3] + bq.y);
            *(float2*)&g_G[(size_t)(r0+8)*NG + col] = v1;
        }
    }
}

// ------------------------ persistent BiLSTM recurrence (tensor-core) ------------------------
#define RC_WHI   0
#define RC_WLO   33280
#define RC_PHI   66560
#define RC_PLO   83200
#define RC_GP    99840
#define RC_C     108032
#define RC_SMEM  108544

__global__ void __launch_bounds__(256) k_recur(const float* __restrict__ whh, int layer, int outparity,
                                               int writeF32, int writePlanes){
    extern __shared__ char smem[];
    unsigned sb = smem_u32(smem);
    float* sGp = (float*)(smem + RC_GP);
    float* sC  = (float*)(smem + RC_C);
    int tid = threadIdx.x;
    int wid = tid >> 5, lane = tid & 31;
    int nw = wid & 1, kw = wid >> 1;
    int dir = blockIdx.x >> 6;
    int bid = blockIdx.x & 63;
    int j0 = bid*8;

    for (int i = tid; i < 4096; i += 256){
        int row = i >> 7;
        int k4  = (i & 127) * 4;
        int g = row >> 3, jj = row & 7;
        float4 w = *(const float4*)&whh[(((size_t)(layer*2+dir))*2048 + g*512 + j0 + jj)*512 + k4];
        unsigned short h0,l0,h1,l1,h2,l2,h3,l3;
        split_bf(w.x,h0,l0); split_bf(w.y,h1,l1); split_bf(w.z,h2,l2); split_bf(w.w,h3,l3);
        *(uint2*)(smem + RC_WHI + row*1040 + k4*2) =
            make_uint2((unsigned)h0 | ((unsigned)h1<<16), (unsigned)h2 | ((unsigned)h3<<16));
        *(uint2*)(smem + RC_WLO + row*1040 + k4*2) =
            make_uint2((unsigned)l0 | ((unsigned)l1<<16), (unsigned)l2 | ((unsigned)l3<<16));
    }
    if (tid < 128) sC[tid] = 0.f;
    __syncthreads();

    unsigned Bh[8][4], Bl[8][4];
    {
        int rowB = nw*16 + (lane & 7) + ((lane >> 4) << 3);
        int chB  = ((lane >> 3) & 1);
        #pragma unroll
        for (int kt = 0; kt < 8; ++kt){
            int ktile = kw*8 + kt;
            unsigned off = rowB*1040 + ktile*32 + chB*16;
            LDSM4(Bh[kt], sb + RC_WHI + off);
            LDSM4(Bl[kt], sb + RC_WLO + off);
        }
    }
    __syncthreads();

    int b2c = tid & 15, jj2c = tid >> 4;
    int colc = dir*2048 + j0 + jj2c;
    float gReg[4] = {0.f,0.f,0.f,0.f};
    if (tid < 128){
        int t0 = dir ? (T_-1) : 0;
        #pragma unroll
        for (int g2 = 0; g2 < 4; ++g2)
            gReg[g2] = g_G[(size_t)(t0*16 + b2c)*NG + colc + g2*512];
    }

    float* xout = g_xbuf[outparity];
    unsigned* cnt = &g_cnt[dir][0];
    int offA_row = (lane & 15)*1040 + (lane >> 4)*16;

    for (int s = 0; s < T_; ++s){
        const unsigned* hin = g_hPk[dir][s & 1];
        #pragma unroll
        for (int it = 0; it < 8; ++it){
            int i = it*256 + tid;
            int b = i >> 7, jq = (i & 127) * 4;
            uint4 v = __ldcg((const uint4*)&hin[b*512 + jq]);
            unsigned hiAB = __byte_perm(v.x, v.y, 0x7632);
            unsigned hiCD = __byte_perm(v.z, v.w, 0x7632);
            unsigned loAB = __byte_perm(v.x, v.y, 0x5410);
            unsigned loCD = __byte_perm(v.z, v.w, 0x5410);
            *(uint2*)(smem + RC_PHI + b*1040 + jq*2) = make_uint2(hiAB, hiCD);
            *(uint2*)(smem + RC_PLO + b*1040 + jq*2) = make_uint2(loAB, loCD);
        }
        __syncthreads();

        float d0[4] = {0.f,0.f,0.f,0.f}, d1[4] = {0.f,0.f,0.f,0.f};
        #pragma unroll
        for (int kt = 0; kt < 8; ++kt){
            int ktile = kw*8 + kt;
            unsigned offA = offA_row + ktile*32;
            unsigned Ah[4], Al[4];
            LDSM4(Ah, sb + RC_PHI + offA);
            LDSM4(Al, sb + RC_PLO + offA);
            MMA16816(d0, Ah, Bh[kt][0], Bh[kt][1]);
            MMA16816(d0, Ah, Bl[kt][0], Bl[kt][1]);
            MMA16816(d0, Al, Bh[kt][0], Bh[kt][1]);
            MMA16816(d1, Ah, Bh[kt][2], Bh[kt][3]);
            MMA16816(d1, Ah, Bl[kt][2], Bl[kt][3]);
            MMA16816(d1, Al, Bh[kt][2], Bh[kt][3]);
        }
        {
            int qr = lane >> 2, qc = lane & 3;
            int row0 = nw*16 + qc*2, row1 = nw*16 + 8 + qc*2;
            *(float2*)&sGp[(kw*16+qr)*32 + row0]   = make_float2(d0[0], d0[1]);
            *(float2*)&sGp[(kw*16+qr+8)*32 + row0] = make_float2(d0[2], d0[3]);
            *(float2*)&sGp[(kw*16+qr)*32 + row1]   = make_float2(d1[0], d1[1]);
            *(float2*)&sGp[(kw*16+qr+8)*32 + row1] = make_float2(d1[2], d1[3]);
        }
        __syncthreads();

        float hval = 0.f; size_t mo = 0; unsigned hh = 0, hl = 0;
        if (tid < 128){
            float ng[4] = {0.f,0.f,0.f,0.f};
            if (s+1 < T_){
                int tn = dir ? (T_-2 - s) : (s+1);
                #pragma unroll
                for (int g2 = 0; g2 < 4; ++g2)
                    ng[g2] = g_G[(size_t)(tn*16 + b2c)*NG + colc + g2*512];
            }
            float acc4[4];
            #pragma unroll
            for (int g2 = 0; g2 < 4; ++g2){
                int row = g2*8 + jj2c;
                float sd = sGp[(0*16 + b2c)*32 + row] + sGp[(1*16 + b2c)*32 + row]
                         + sGp[(2*16 + b2c)*32 + row] + sGp[(3*16 + b2c)*32 + row];
                acc4[g2] = gReg[g2] + sd;
            }
            float c = sigf(acc4[1])*sC[tid] + sigf(acc4[0])*tanhf(acc4[2]);
            sC[tid] = c;
            hval = sigf(acc4[3])*tanhf(c);
            __nv_bfloat16 hb = __float2bfloat16(hval);
            hh = __bfloat16_as_ushort(hb);
            hl = __bfloat16_as_ushort(__float2bfloat16(hval - __bfloat162float(hb)));
            g_hPk[dir][(s+1)&1][b2c*512 + j0 + jj2c] = (hh << 16) | hl;
            int t2 = dir ? (T_-1 - s) : s;
            mo = (size_t)(t2*16 + b2c)*1024 + dir*512 + j0 + jj2c;
            gReg[0] = ng[0]; gReg[1] = ng[1]; gReg[2] = ng[2]; gReg[3] = ng[3];
        }
        __syncthreads();
        if (tid == 0){
            asm volatile("red.release.gpu.global.add.u32 [%0], %1;"
                         :: "l"(&cnt[s]), "r"(1u) : "memory");
        }
        if (tid < 128){
            if (writeF32) xout[mo] = hval;
            if (writePlanes){
                g_Xhi[mo] = (unsigned short)hh;
                g_Xlo[mo] = (unsigned short)hl;
            }
        }
        if (tid == 0){
            unsigned v;
            do {
                asm volatile("ld.acquire.gpu.global.u32 %0, [%1];"
                             : "=r"(v) : "l"(&cnt[s]) : "memory");
            } while (v < 64u);
        }
        __syncthreads();
    }
}

// ------------------------ classifier ------------------------
__global__ void __launch_bounds__(256) k_cls(const float* __restrict__ cls_w,
                                             const float* __restrict__ cls_b, int parity){
    __shared__ float sW[L_][1024];
    __shared__ float sB[L_];
    int tid = threadIdx.x;
    for (int i = tid; i < L_*1024; i += 256) ((float*)sW)[i] = cls_w[i];
    if (tid < L_) sB[tid] = cls_b[tid];
    __syncthreads();
    int m = blockIdx.x*256 + tid;
    const float* xr = &g_xbuf[parity][(size_t)m*1024];
    float acc[L_];
    #pragma unroll
    for (int l=0;l<L_;l++) acc[l] = sB[l];
    for (int k = 0; k < 1024; k += 4){
        float4 xv = *(const float4*)&xr[k];
        #pragma unroll
        for (int l=0;l<L_;l++){
            float4 wv = *(const float4*)&sW[l][k];
            acc[l] += xv.x*wv.x + xv.y*wv.y + xv.z*wv.z + xv.w*wv.w;
        }
    }
    #pragma unroll
    for (int l=0;l<L_;l++) g_logits[m*L_ + l] = acc[l];
}

// ------------------------ CRF NLL (one block) ------------------------
__global__ void __launch_bounds__(128) k_crf(const int* __restrict__ att, const int* __restrict__ lab,
                                             const float* __restrict__ startv, const float* __restrict__ endv,
                                             const float* __restrict__ trans, float* __restrict__ out){
    __shared__ float sT[36], sS[6], sE[6];
    __shared__ float sAl[16][6];
    __shared__ float sNum[16], sLoss[16];
    int tid = threadIdx.x;
    if (tid < 36) sT[tid] = trans[tid];
    if (tid < 6){ sS[tid] = startv[tid]; sE[tid] = endv[tid]; }
    __syncthreads();

    bool isDen = tid < 96;
    bool isNum = (tid >= 96) && (tid < 112);
    int b = isDen ? tid/6 : tid-96;
    int j = tid % 6;

    float score = 0.f; int prev = 0;
    if (isDen) sAl[b][j] = sS[j] + g_logits[b*L_ + j];
    if (isNum){
        int l0 = lab[b*T_];
        int t0 = (l0 == -100) ? 0 : l0;
        score = sS[t0] + g_logits[b*L_ + t0];
        prev = t0;
    }
    __syncthreads();

    for (int t = 1; t < T_; ++t){
        float nxt = 0.f; bool mk = false;
        if (isDen){
            mk = (att[b*T_ + t] != 0) && (lab[b*T_ + t] != -100);
            float e = g_logits[(t*16 + b)*L_ + j];
            float mx = -1e30f;
            #pragma unroll
            for (int i2=0;i2<6;i2++) mx = fmaxf(mx, sAl[b][i2] + sT[i2*6+j]);
            float ss = 0.f;
            #pragma unroll
            for (int i2=0;i2<6;i2++) ss += expf(sAl[b][i2] + sT[i2*6+j] - mx);
            nxt = mx + logf(ss) + e;
        } else if (isNum){
            int lb = lab[b*T_ + t];
            bool m = (att[b*T_ + t] != 0) && (lb != -100);
            int tt = (lb == -100) ? 0 : lb;
            if (m){
                score += sT[prev*6 + tt] + g_logits[(t*16 + b)*L_ + tt];
                prev = tt;
            }
        }
        __syncthreads();
        if (isDen && mk) sAl[b][j] = nxt;
        __syncthreads();
    }

    if (isNum) sNum[b] = score + sE[prev];
    __syncthreads();
    if (tid < 16){
        float mx = -1e30f;
        #pragma unroll
        for (int jj=0;jj<6;jj++) mx = fmaxf(mx, sAl[tid][jj] + sE[jj]);
        float ss = 0.f;
        #pragma unroll
        for (int jj=0;jj<6;jj++) ss += expf(sAl[tid][jj] + sE[jj] - mx);
        float den = mx + logf(ss);
        sLoss[tid] = den - sNum[tid];
    }
    __syncthreads();
    if (tid == 0){
        float s = 0.f;
        for (int i=0;i<16;i++) s += sLoss[i];
        out[0] = s / 16.f;
    }
}

// ------------------------ launch ------------------------
extern "C" void kernel_launch(void* const* d_in, const int* in_sizes, int n_in,
                              void* d_out, int out_size){
    const float* emb    = (const float*)d_in[0];
    const int*   att    = (const int*)  d_in[1];
    const int*   lab    = (const int*)  d_in[2];
    const float* conv_w = (const float*)d_in[3];
    const float* conv_b = (const float*)d_in[4];
    const float* bn_g   = (const float*)d_in[5];
    const float* bn_b   = (const float*)d_in[6];
    const float* bn_m   = (const float*)d_in[7];
    const float* bn_v   = (const float*)d_in[8];
    const float* wih    = (const float*)d_in[9];
    const float* whh    = (const float*)d_in[10];
    const float* bih    = (const float*)d_in[11];
    const float* bhh    = (const float*)d_in[12];
    const float* cls_w  = (const float*)d_in[13];
    const float* cls_b  = (const float*)d_in[14];
    const float* crf_s  = (const float*)d_in[15];
    const float* crf_e  = (const float*)d_in[16];
    const float* crf_t  = (const float*)d_in[17];
    float* out = (float*)d_out;

    cudaFuncSetAttribute(k_recur, cudaFuncAttributeMaxDynamicSharedMemorySize, RC_SMEM);
    cudaFuncSetAttribute(k_gate,  cudaFuncAttributeMaxDynamicSharedMemorySize, GT_SMEM);
    cudaFuncSetAttribute(k_convT, cudaFuncAttributeMaxDynamicSharedMemorySize, GT_SMEM);

    k_cvt_e <<<B_*T_*E_/256, 256>>>(emb);
    k_cvt_cw<<<C_*KC_/256, 256>>>(conv_w);
    k_cvt_w <<<3*NG*KI/256, 256>>>(wih);
    k_pack_small<<<48, 256>>>(bih, bhh, bn_g, bn_b, bn_m, bn_v, conv_b);

    k_convT<<<dim3(C_/128, M_/128), 256, GT_SMEM>>>();

    for (int l = 0; l < 3; ++l){
        int outpar = (l + 1) & 1;
        int wF32    = (l == 2) ? 1 : 0;
        int wPlanes = (l == 2) ? 0 : 1;
        k_gate<<<dim3(NG/128, M_/128), 256, GT_SMEM>>>(l);
        k_reset<<<128, 256>>>();
        k_recur<<<128, 256, RC_SMEM>>>(whh, l, outpar, wF32, wPlanes);
    }

    k_cls<<<M_/256, 256>>>(cls_w, cls_b, 1);
    k_crf<<<1, 128>>>(att, lab, crf_s, crf_e, crf_t, out);
}

// round 13
// speedup vs baseline: 1.8197x; 1.0133x over previous
#include <cuda_runtime.h>
#include <cuda_bf16.h>
#include <math.h>
#include <cstdint>

typedef unsigned long long ull;

#define T_ 1024
#define B_ 16
#define E_ 1024
#define H_ 512
#define C_ 1024
#define L_ 6
#define M_ (T_*B_)
#define NG 4096
#define KI 1024
#define KC_ (5*E_)              // 5120 conv GEMM K

// ------------------------ device scratch ------------------------
__device__ float g_xbuf[2][(size_t)M_*C_];       // fp32 activations (layer-3 out / classifier in)
__device__ float g_G[(size_t)M_*NG];             // input-projected gates [m][4096]
__device__ unsigned short g_Xhi[(size_t)M_*KI];  // bf16 hi plane of activations
__device__ unsigned short g_Xlo[(size_t)M_*KI];  // bf16 lo plane
__device__ unsigned short g_Whi[3][(size_t)NG*KI]; // bf16 hi of wih ([n][k] layout)
__device__ unsigned short g_Wlo[3][(size_t)NG*KI];
__device__ unsigned short g_Ehi[(size_t)B_*T_*E_]; // bf16 hi of embeddings
__device__ unsigned short g_Elo[(size_t)B_*T_*E_];
__device__ unsigned short g_CWhi[(size_t)C_*KC_];  // conv w planes, [c][dk*1024+e]
__device__ unsigned short g_CWlo[(size_t)C_*KC_];
__device__ float g_biasG[3][NG];
__device__ float g_bnA[C_], g_bnB[C_];
__device__ unsigned g_hPk[2][2][H_*B_];          // packed h: (bf16hi<<16)|bf16lo, [b*512+j]
__device__ unsigned g_cnt[2][T_];
__device__ float g_logits[M_*L_];

// ------------------------ helpers ------------------------
__device__ __forceinline__ float sigf(float x){ return 1.f/(1.f + expf(-x)); }
__device__ __forceinline__ float sigf_fast(float x){ return __fdividef(1.f, 1.f + __expf(-x)); }
__device__ __forceinline__ float tanh_fast(float x){ return 1.f - __fdividef(2.f, __expf(2.f*x) + 1.f); }

__device__ __forceinline__ void split_bf(float v, unsigned short& h, unsigned short& l){
    __nv_bfloat16 hb = __float2bfloat16(v);
    h = __bfloat16_as_ushort(hb);
    l = __bfloat16_as_ushort(__float2bfloat16(v - __bfloat162float(hb)));
}

__device__ __forceinline__ unsigned smem_u32(const void* p){
    unsigned a; asm("{ .reg .u64 t; cvta.to.shared.u64 t, %1; cvt.u32.u64 %0, t; }" : "=r"(a) : "l"(p));
    return a;
}

#define LDSM4(r, a) \
    asm volatile("ldmatrix.sync.aligned.m8n8.x4.shared.b16 {%0,%1,%2,%3}, [%4];" \
        : "=r"((r)[0]),"=r"((r)[1]),"=r"((r)[2]),"=r"((r)[3]) : "r"(a))

#define MMA16816(dd, A, b0, b1) \
    asm volatile("mma.sync.aligned.m16n8k16.row.col.f32.bf16.bf16.f32 " \
        "{%0,%1,%2,%3}, {%4,%5,%6,%7}, {%8,%9}, {%0,%1,%2,%3};" \
        : "+f"((dd)[0]),"+f"((dd)[1]),"+f"((dd)[2]),"+f"((dd)[3]) \
        : "r"((A)[0]),"r"((A)[1]),"r"((A)[2]),"r"((A)[3]), "r"(b0),"r"(b1))

// ------------------------ pack / convert kernels ------------------------
__global__ void k_cvt_e(const float* __restrict__ emb){
    size_t idx = (size_t)blockIdx.x*256 + threadIdx.x;
    float v = emb[idx];
    unsigned short h, l; split_bf(v, h, l);
    g_Ehi[idx] = h;
    g_Elo[idx] = l;
}

__global__ void k_cvt_cw(const float* __restrict__ cw){
    size_t idx = (size_t)blockIdx.x*256 + threadIdx.x;
    int c  = (int)(idx / KC_);
    int kk = (int)(idx - (size_t)c*KC_);
    int dk = kk >> 10, e = kk & 1023;
    float v = cw[((size_t)c*E_ + e)*5 + dk];
    unsigned short h, l; split_bf(v, h, l);
    g_CWhi[idx] = h;
    g_CWlo[idx] = l;
}

__global__ void k_cvt_w(const float* __restrict__ wih){
    size_t idx = (size_t)blockIdx.x*256 + threadIdx.x;
    float v = wih[idx];
    unsigned short h, l; split_bf(v, h, l);
    ((unsigned short*)g_Whi)[idx] = h;
    ((unsigned short*)g_Wlo)[idx] = l;
}

__global__ void k_pack_small(const float* __restrict__ bih, const float* __restrict__ bhh,
                             const float* __restrict__ gamma, const float* __restrict__ beta,
                             const float* __restrict__ mean, const float* __restrict__ var,
                             const float* __restrict__ convb){
    int idx = blockIdx.x*256 + threadIdx.x;
    if (idx < 3*NG){
        int l = idx / NG; int n = idx - l*NG;
        int dir = n >> 11, r = n & 2047;
        int src = (l*2+dir)*2048 + r;
        ((float*)g_biasG)[idx] = bih[src] + bhh[src];
    }
    if (idx < C_){
        float s = gamma[idx] * rsqrtf(var[idx] + 1e-5f);
        g_bnA[idx] = s;
        g_bnB[idx] = s*convb[idx] + beta[idx] - mean[idx]*s;
    }
}

__global__ void k_reset(){
    int idx = blockIdx.x*256 + threadIdx.x;
    if (idx < 2*2*H_*B_) ((unsigned*)g_hPk)[idx] = 0u;
    if (idx < 2*T_) ((unsigned*)g_cnt)[idx] = 0u;
}

// ------------------------ shared HMMA tile layout ------------------------
#define PLANE_B 10240            // 128*80
#define STAGE_B (4*PLANE_B)      // 40960
#define GT_SMEM (2*STAGE_B)      // 81920

// ------------------------ split-bf16 HMMA conv GEMM + BN + ReLU ------------------------
__global__ void __launch_bounds__(256) k_convT(){
    extern __shared__ char smem[];
    unsigned sbase = smem_u32(smem);
    int tid = threadIdx.x;
    int wid = tid >> 5, lane = tid & 31;
    int m0 = blockIdx.y*128, n0 = blockIdx.x*128;

    auto prefetch = [&](int kc, int stg){
        unsigned sb = sbase + stg*STAGE_B;
        int dk = (kc*32) >> 10;
        int e_base = (kc*32) & 1023;
        #pragma unroll
        for (int it = 0; it < 8; ++it){
            int i = it*256 + tid;
            int p = i >> 9, rem = i & 511;
            int row = rem >> 2, c = rem & 3;
            unsigned sa = sb + p*PLANE_B + row*80 + c*16;
            if (p < 2){
                int m = m0 + row;
                int t = m >> 4, b = m & 15;
                int tp = t + dk - 2;
                const unsigned short* base = (p == 0) ? g_Ehi : g_Elo;
                const void* ga = base + ((size_t)b*1024 + tp)*1024 + e_base + c*8;
                unsigned sz = ((unsigned)tp < 1024u) ? 16u : 0u;
                asm volatile("cp.async.cg.shared.global [%0], [%1], 16, %2;"
                             :: "r"(sa), "l"(ga), "r"(sz) : "memory");
            } else {
                const unsigned short* base = (p == 2) ? g_CWhi : g_CWlo;
                const void* ga = base + (size_t)(n0 + row)*KC_ + kc*32 + c*8;
                asm volatile("cp.async.cg.shared.global [%0], [%1], 16;"
                             :: "r"(sa), "l"(ga) : "memory");
            }
        }
        asm volatile("cp.async.commit_group;" ::: "memory");
    };

    int wm = wid >> 1, wn = wid & 1;
    float d[2][8][4];
    #pragma unroll
    for (int mi=0;mi<2;++mi)
        #pragma unroll
        for (int ni=0;ni<8;++ni)
            #pragma unroll
            for (int q=0;q<4;++q) d[mi][ni][q] = 0.f;

    prefetch(0, 0);

    for (int kt = 0; kt < KC_/32; ++kt){
        int stg = kt & 1;
        asm volatile("cp.async.wait_group 0;" ::: "memory");
        __syncthreads();
        if (kt + 1 < KC_/32) prefetch(kt + 1, stg ^ 1);

        unsigned sb  = sbase + stg*STAGE_B;
        unsigned aHi = sb,            aLo = sb + PLANE_B;
        unsigned bHi = sb + 2*PLANE_B, bLo = sb + 3*PLANE_B;

        #pragma unroll
        for (int kh = 0; kh < 2; ++kh){
            unsigned Ah[2][4], Al[2][4];
            #pragma unroll
            for (int mi = 0; mi < 2; ++mi){
                int row = wm*32 + mi*16 + (lane & 15);
                int ch  = kh*2 + (lane >> 4);
                unsigned off = row*80 + ch*16;
                LDSM4(Ah[mi], aHi + off);
                LDSM4(Al[mi], aLo + off);
            }
            unsigned Bh[4][4], Bl[4][4];
            #pragma unroll
            for (int pr = 0; pr < 4; ++pr){
                int row = wn*64 + pr*16 + (lane & 7) + ((lane >> 4) << 3);
                int ch  = kh*2 + ((lane >> 3) & 1);
                unsigned off = row*80 + ch*16;
                LDSM4(Bh[pr], bHi + off);
                LDSM4(Bl[pr], bLo + off);
            }
            #pragma unroll
            for (int mi = 0; mi < 2; ++mi){
                #pragma unroll
                for (int pr = 0; pr < 4; ++pr){
                    MMA16816(d[mi][2*pr],   Ah[mi], Bh[pr][0], Bh[pr][1]);
                    MMA16816(d[mi][2*pr],   Ah[mi], Bl[pr][0], Bl[pr][1]);
                    MMA16816(d[mi][2*pr],   Al[mi], Bh[pr][0], Bh[pr][1]);
                    MMA16816(d[mi][2*pr+1], Ah[mi], Bh[pr][2], Bh[pr][3]);
                    MMA16816(d[mi][2*pr+1], Ah[mi], Bl[pr][2], Bl[pr][3]);
                    MMA16816(d[mi][2*pr+1], Al[mi], Bh[pr][2], Bh[pr][3]);
                }
            }
        }
    }

    int qr = lane >> 2, qc = lane & 3;
    #pragma unroll
    for (int mi = 0; mi < 2; ++mi){
        #pragma unroll
        for (int ni = 0; ni < 8; ++ni){
            int col = n0 + wn*64 + ni*8 + qc*2;
            float2 A = *(const float2*)&g_bnA[col];
            float2 Bb = *(const float2*)&g_bnB[col];
            int r0 = m0 + wm*32 + mi*16 + qr;
            float v00 = fmaxf(d[mi][ni][0]*A.x + Bb.x, 0.f);
            float v01 = fmaxf(d[mi][ni][1]*A.y + Bb.y, 0.f);
            float v10 = fmaxf(d[mi][ni][2]*A.x + Bb.x, 0.f);
            float v11 = fmaxf(d[mi][ni][3]*A.y + Bb.y, 0.f);
            ushort2 h0, l0, h1, l1;
            split_bf(v00, h0.x, l0.x); split_bf(v01, h0.y, l0.y);
            split_bf(v10, h1.x, l1.x); split_bf(v11, h1.y, l1.y);
            *(ushort2*)&g_Xhi[(size_t)r0*1024 + col]     = h0;
            *(ushort2*)&g_Xlo[(size_t)r0*1024 + col]     = l0;
            *(ushort2*)&g_Xhi[(size_t)(r0+8)*1024 + col] = h1;
            *(ushort2*)&g_Xlo[(size_t)(r0+8)*1024 + col] = l1;
        }
    }
}

// ------------------------ mma.sync split-bf16 gate GEMM ------------------------
__global__ void __launch_bounds__(256) k_gate(int layer){
    extern __shared__ char smem[];
    unsigned sbase = smem_u32(smem);
    int tid = threadIdx.x;
    int wid = tid >> 5, lane = tid & 31;
    int m0 = blockIdx.y*128, n0 = blockIdx.x*128;

    const unsigned short* srcs[4] = {
        g_Xhi + (size_t)m0*1024,
        g_Xlo + (size_t)m0*1024,
        g_Whi[layer] + (size_t)n0*1024,
        g_Wlo[layer] + (size_t)n0*1024
    };

    auto prefetch = [&](int kc, int stg){
        unsigned sb = sbase + stg*STAGE_B;
        #pragma unroll
        for (int it = 0; it < 8; ++it){
            int i = it*256 + tid;
            int p = i >> 9, rem = i & 511;
            int row = rem >> 2, c = rem & 3;
            unsigned sa = sb + p*PLANE_B + row*80 + c*16;
            const void* ga = srcs[p] + (size_t)row*1024 + kc*32 + c*8;
            asm volatile("cp.async.cg.shared.global [%0], [%1], 16;" :: "r"(sa), "l"(ga) : "memory");
        }
        asm volatile("cp.async.commit_group;" ::: "memory");
    };

    int wm = wid >> 1, wn = wid & 1;
    float d[2][8][4];
    #pragma unroll
    for (int mi=0;mi<2;++mi)
        #pragma unroll
        for (int ni=0;ni<8;++ni)
            #pragma unroll
            for (int q=0;q<4;++q) d[mi][ni][q] = 0.f;

    prefetch(0, 0);

    for (int kt = 0; kt < 32; ++kt){
        int stg = kt & 1;
        asm volatile("cp.async.wait_group 0;" ::: "memory");
        __syncthreads();
        if (kt + 1 < 32) prefetch(kt + 1, stg ^ 1);

        unsigned sb  = sbase + stg*STAGE_B;
        unsigned aHi = sb,            aLo = sb + PLANE_B;
        unsigned bHi = sb + 2*PLANE_B, bLo = sb + 3*PLANE_B;

        #pragma unroll
        for (int kh = 0; kh < 2; ++kh){
            unsigned Ah[2][4], Al[2][4];
            #pragma unroll
            for (int mi = 0; mi < 2; ++mi){
                int row = wm*32 + mi*16 + (lane & 15);
                int ch  = kh*2 + (lane >> 4);
                unsigned off = row*80 + ch*16;
                LDSM4(Ah[mi], aHi + off);
                LDSM4(Al[mi], aLo + off);
            }
            unsigned Bh[4][4], Bl[4][4];
            #pragma unroll
            for (int pr = 0; pr < 4; ++pr){
                int row = wn*64 + pr*16 + (lane & 7) + ((lane >> 4) << 3);
                int ch  = kh*2 + ((lane >> 3) & 1);
                unsigned off = row*80 + ch*16;
                LDSM4(Bh[pr], bHi + off);
                LDSM4(Bl[pr], bLo + off);
            }
            #pragma unroll
            for (int mi = 0; mi < 2; ++mi){
                #pragma unroll
                for (int pr = 0; pr < 4; ++pr){
                    MMA16816(d[mi][2*pr],   Ah[mi], Bh[pr][0], Bh[pr][1]);
                    MMA16816(d[mi][2*pr],   Ah[mi], Bl[pr][0], Bl[pr][1]);
                    MMA16816(d[mi][2*pr],   Al[mi], Bh[pr][0], Bh[pr][1]);
                    MMA16816(d[mi][2*pr+1], Ah[mi], Bh[pr][2], Bh[pr][3]);
                    MMA16816(d[mi][2*pr+1], Ah[mi], Bl[pr][2], Bl[pr][3]);
                    MMA16816(d[mi][2*pr+1], Al[mi], Bh[pr][2], Bh[pr][3]);
                }
            }
        }
    }

    int qr = lane >> 2, qc = lane & 3;
    #pragma unroll
    for (int mi = 0; mi < 2; ++mi){
        #pragma unroll
        for (int ni = 0; ni < 8; ++ni){
            int col = n0 + wn*64 + ni*8 + qc*2;
            float2 bq = *(const float2*)&g_biasG[layer][col];
            int r0 = m0 + wm*32 + mi*16 + qr;
            float2 v0 = make_float2(d[mi][ni][0] + bq.x, d[mi][ni][1] + bq.y);
            *(float2*)&g_G[(size_t)r0*NG + col] = v0;
            float2 v1 = make_float2(d[mi][ni][2] + bq.x, d[mi][ni][3] + bq.y);
            *(float2*)&g_G[(size_t)(r0+8)*NG + col] = v1;
        }
    }
}

// ------------------------ persistent BiLSTM recurrence (fused fw+bw, warp-specialized) ------------------------
// 64 blocks, 256 threads. Warps 0-3 = forward half, warps 4-7 = backward half.
// Each half: 32 gate rows {g*512 + j0+jj}, j0 = bid*8; K=512 split 2-way (kw),
// rows split 2-way (nw). Whh bf16 fragments register-resident (staged via smem
// in two 16-row chunks). Halves sync independently with named barriers, so one
// half's barrier-poll latency is hidden under the other half's compute.
// smem per half: h planes PHI+PLO 16x1040 x2 = 33280 | sGp 4096 | sC 512
#define R2_PH(h)   ((h)*33280)
#define R2_GP(h)   (66560 + (h)*4096)
#define R2_C(h)    (74752 + (h)*512)
#define R2_SMEM    75776

__global__ void __launch_bounds__(256) k_recur2(const float* __restrict__ whh, int layer, int outparity,
                                                int writeF32, int writePlanes){
    extern __shared__ char smem[];
    unsigned sb = smem_u32(smem);
    int tid = threadIdx.x;
    int half = tid >> 7;                 // 0 = fw, 1 = bw
    int htid = tid & 127;
    int hwid = htid >> 5;                // 0..3 within half
    int lane = tid & 31;
    int kw = hwid & 1, nw = hwid >> 1;   // K-half, row-half
    int dir = half;
    int bid = blockIdx.x;
    int j0 = bid*8;

    unsigned phBase = sb + R2_PH(half);          // PHI = phBase, PLO = phBase+16640
    float* sGp = (float*)(smem + R2_GP(half));
    float* sC  = (float*)(smem + R2_C(half));

    // ---- stage Whh (two 16-row chunks through h-plane region) + preload B frags ----
    unsigned Bh[16][4], Bl[16][4];
    for (int c = 0; c < 2; ++c){
        for (int i = htid; i < 2048; i += 128){      // 16 rows x 128 float4
            int row = i >> 7;
            int k4  = (i & 127) * 4;
            int grow = c*16 + row;
            int g = grow >> 3, jj = grow & 7;
            float4 w = *(const float4*)&whh[(((size_t)(layer*2+dir))*2048 + g*512 + j0 + jj)*512 + k4];
            unsigned short h0,l0,h1,l1,h2,l2,h3,l3;
            split_bf(w.x,h0,l0); split_bf(w.y,h1,l1); split_bf(w.z,h2,l2); split_bf(w.w,h3,l3);
            *(uint2*)(smem + R2_PH(half) + row*1040 + k4*2) =
                make_uint2((unsigned)h0 | ((unsigned)h1<<16), (unsigned)h2 | ((unsigned)h3<<16));
            *(uint2*)(smem + R2_PH(half) + 16640 + row*1040 + k4*2) =
                make_uint2((unsigned)l0 | ((unsigned)l1<<16), (unsigned)l2 | ((unsigned)l3<<16));
        }
        __syncthreads();
        if (nw == c){
            int rowB = (lane & 7) + ((lane >> 4) << 3);   // chunk-local 0..15
            int chB  = (lane >> 3) & 1;
            #pragma unroll
            for (int kt = 0; kt < 16; ++kt){
                int ktile = kw*16 + kt;
                unsigned off = rowB*1040 + ktile*32 + chB*16;
                LDSM4(Bh[kt], phBase + off);
                LDSM4(Bl[kt], phBase + 16640 + off);
            }
        }
        __syncthreads();
    }
    if (htid < 128) sC[htid] = 0.f;
    __syncthreads();

    // ---- cell-thread state (all 128 half-threads) ----
    int b2c = htid & 15, jj2c = htid >> 4;
    int colc = dir*2048 + j0 + jj2c;
    float gReg[4];
    {
        int t0 = dir ? (T_-1) : 0;
        #pragma unroll
        for (int g2 = 0; g2 < 4; ++g2)
            gReg[g2] = g_G[(size_t)(t0*16 + b2c)*NG + colc + g2*512];
    }

    float* xout = g_xbuf[outparity];
    unsigned* cnt = &g_cnt[dir][0];
    int offA_row = (lane & 15)*1040 + (lane >> 4)*16;
    int barid = 1 + half;

    for (int s = 0; s < T_; ++s){
        // stage packed h -> bf16 planes (this half's direction)
        const unsigned* hin = g_hPk[dir][s & 1];
        #pragma unroll
        for (int it = 0; it < 16; ++it){
            int i = it*128 + htid;                   // 0..2047 uint4
            int b = i >> 7, jq = (i & 127) * 4;
            uint4 v = __ldcg((const uint4*)&hin[b*512 + jq]);
            unsigned hiAB = __byte_perm(v.x, v.y, 0x7632);
            unsigned hiCD = __byte_perm(v.z, v.w, 0x7632);
            unsigned loAB = __byte_perm(v.x, v.y, 0x5410);
            unsigned loCD = __byte_perm(v.z, v.w, 0x5410);
            *(uint2*)(smem + R2_PH(half) + b*1040 + jq*2) = make_uint2(hiAB, hiCD);
            *(uint2*)(smem + R2_PH(half) + 16640 + b*1040 + jq*2) = make_uint2(loAB, loCD);
        }
        asm volatile("bar.sync %0, 128;" :: "r"(barid) : "memory");

        // MMA: 3-term split, K=256 per warp, n=16 rows per warp
        float d0[4] = {0.f,0.f,0.f,0.f}, d1[4] = {0.f,0.f,0.f,0.f};
        #pragma unroll
        for (int kt = 0; kt < 16; ++kt){
            int ktile = kw*16 + kt;
            unsigned offA = offA_row + ktile*32;
            unsigned Ah[4], Al[4];
            LDSM4(Ah, phBase + offA);
            LDSM4(Al, phBase + 16640 + offA);
            MMA16816(d0, Ah, Bh[kt][0], Bh[kt][1]);
            MMA16816(d0, Ah, Bl[kt][0], Bl[kt][1]);
            MMA16816(d0, Al, Bh[kt][0], Bh[kt][1]);
            MMA16816(d1, Ah, Bh[kt][2], Bh[kt][3]);
            MMA16816(d1, Ah, Bl[kt][2], Bl[kt][3]);
            MMA16816(d1, Al, Bh[kt][2], Bh[kt][3]);
        }
        {
            int qr = lane >> 2, qc = lane & 3;
            int row0 = nw*16 + qc*2, row1 = nw*16 + 8 + qc*2;
            *(float2*)&sGp[(kw*16+qr)*32 + row0]   = make_float2(d0[0], d0[1]);
            *(float2*)&sGp[(kw*16+qr+8)*32 + row0] = make_float2(d0[2], d0[3]);
            *(float2*)&sGp[(kw*16+qr)*32 + row1]   = make_float2(d1[0], d1[1]);
            *(float2*)&sGp[(kw*16+qr+8)*32 + row1] = make_float2(d1[2], d1[3]);
        }
        asm volatile("bar.sync %0, 128;" :: "r"(barid) : "memory");

        // cell update (all 128 half-threads)
        float hval; size_t mo; unsigned hh, hl;
        {
            float ng[4] = {0.f,0.f,0.f,0.f};
            if (s+1 < T_){
                int tn = dir ? (T_-2 - s) : (s+1);
                #pragma unroll
                for (int g2 = 0; g2 < 4; ++g2)
                    ng[g2] = g_G[(size_t)(tn*16 + b2c)*NG + colc + g2*512];
            }
            float acc4[4];
            #pragma unroll
            for (int g2 = 0; g2 < 4; ++g2){
                int row = g2*8 + jj2c;
                float sd = sGp[(0*16 + b2c)*32 + row] + sGp[(1*16 + b2c)*32 + row];
                acc4[g2] = gReg[g2] + sd;
            }
            float c = sigf_fast(acc4[1])*sC[htid] + sigf_fast(acc4[0])*tanh_fast(acc4[2]);
            sC[htid] = c;
            hval = sigf_fast(acc4[3])*tanh_fast(c);
            __nv_bfloat16 hb = __float2bfloat16(hval);
            hh = __bfloat16_as_ushort(hb);
            hl = __bfloat16_as_ushort(__float2bfloat16(hval - __bfloat162float(hb)));
            g_hPk[dir][(s+1)&1][b2c*512 + j0 + jj2c] = (hh << 16) | hl;
            int t2 = dir ? (T_-1 - s) : s;
            mo = (size_t)(t2*16 + b2c)*1024 + dir*512 + j0 + jj2c;
            gReg[0] = ng[0]; gReg[1] = ng[1]; gReg[2] = ng[2]; gReg[3] = ng[3];
        }
        asm volatile("bar.sync %0, 128;" :: "r"(barid) : "memory");
        if (htid == 0){
            asm volatile("red.release.gpu.global.add.u32 [%0], %1;"
                         :: "l"(&cnt[s]), "r"(1u) : "memory");
        }
        // deferred next-layer output stores (outside the release chain)
        {
            if (writeF32) xout[mo] = hval;
            if (writePlanes){
                g_Xhi[mo] = (unsigned short)hh;
                g_Xlo[mo] = (unsigned short)hl;
            }
        }
        if (htid == 0){
            unsigned v;
            do {
                asm volatile("ld.acquire.gpu.global.u32 %0, [%1];"
                             : "=r"(v) : "l"(&cnt[s]) : "memory");
            } while (v < 64u);
        }
        asm volatile("bar.sync %0, 128;" :: "r"(barid) : "memory");
    }
}

// ------------------------ classifier ------------------------
__global__ void __launch_bounds__(256) k_cls(const float* __restrict__ cls_w,
                                             const float* __restrict__ cls_b, int parity){
    __shared__ float sW[L_][1024];
    __shared__ float sB[L_];
    int tid = threadIdx.x;
    for (int i = tid; i < L_*1024; i += 256) ((float*)sW)[i] = cls_w[i];
    if (tid < L_) sB[tid] = cls_b[tid];
    __syncthreads();
    int m = blockIdx.x*256 + tid;
    const float* xr = &g_xbuf[parity][(size_t)m*1024];
    float acc[L_];
    #pragma unroll
    for (int l=0;l<L_;l++) acc[l] = sB[l];
    for (int k = 0; k < 1024; k += 4){
        float4 xv = *(const float4*)&xr[k];
        #pragma unroll
        for (int l=0;l<L_;l++){
            float4 wv = *(const float4*)&sW[l][k];
            acc[l] += xv.x*wv.x + xv.y*wv.y + xv.z*wv.z + xv.w*wv.w;
        }
    }
    #pragma unroll
    for (int l=0;l<L_;l++) g_logits[m*L_ + l] = acc[l];
}

// ------------------------ CRF NLL (one block) ------------------------
__global__ void __launch_bounds__(128) k_crf(const int* __restrict__ att, const int* __restrict__ lab,
                                             const float* __restrict__ startv, const float* __restrict__ endv,
                                             const float* __restrict__ trans, float* __restrict__ out){
    __shared__ float sT[36], sS[6], sE[6];
    __shared__ float sAl[16][6];
    __shared__ float sNum[16], sLoss[16];
    int tid = threadIdx.x;
    if (tid < 36) sT[tid] = trans[tid];
    if (tid < 6){ sS[tid] = startv[tid]; sE[tid] = endv[tid]; }
    __syncthreads();

    bool isDen = tid < 96;
    bool isNum = (tid >= 96) && (tid < 112);
    int b = isDen ? tid/6 : tid-96;
    int j = tid % 6;

    float score = 0.f; int prev = 0;
    if (isDen) sAl[b][j] = sS[j] + g_logits[b*L_ + j];
    if (isNum){
        int l0 = lab[b*T_];
        int t0 = (l0 == -100) ? 0 : l0;
        score = sS[t0] + g_logits[b*L_ + t0];
        prev = t0;
    }
    __syncthreads();

    for (int t = 1; t < T_; ++t){
        float nxt = 0.f; bool mk = false;
        if (isDen){
            mk = (att[b*T_ + t] != 0) && (lab[b*T_ + t] != -100);
            float e = g_logits[(t*16 + b)*L_ + j];
            float mx = -1e30f;
            #pragma unroll
            for (int i2=0;i2<6;i2++) mx = fmaxf(mx, sAl[b][i2] + sT[i2*6+j]);
            float ss = 0.f;
            #pragma unroll
            for (int i2=0;i2<6;i2++) ss += expf(sAl[b][i2] + sT[i2*6+j] - mx);
            nxt = mx + logf(ss) + e;
        } else if (isNum){
            int lb = lab[b*T_ + t];
            bool m = (att[b*T_ + t] != 0) && (lb != -100);
            int tt = (lb == -100) ? 0 : lb;
            if (m){
                score += sT[prev*6 + tt] + g_logits[(t*16 + b)*L_ + tt];
                prev = tt;
            }
        }
        __syncthreads();
        if (isDen && mk) sAl[b][j] = nxt;
        __syncthreads();
    }

    if (isNum) sNum[b] = score + sE[prev];
    __syncthreads();
    if (tid < 16){
        float mx = -1e30f;
        #pragma unroll
        for (int jj=0;jj<6;jj++) mx = fmaxf(mx, sAl[tid][jj] + sE[jj]);
        float ss = 0.f;
        #pragma unroll
        for (int jj=0;jj<6;jj++) ss += expf(sAl[tid][jj] + sE[jj] - mx);
        float den = mx + logf(ss);
        sLoss[tid] = den - sNum[tid];
    }
    __syncthreads();
    if (tid == 0){
        float s = 0.f;
        for (int i=0;i<16;i++) s += sLoss[i];
        out[0] = s / 16.f;
    }
}

// ------------------------ launch ------------------------
extern "C" void kernel_launch(void* const* d_in, const int* in_sizes, int n_in,
                              void* d_out, int out_size){
    const float* emb    = (const float*)d_in[0];
    const int*   att    = (const int*)  d_in[1];
    const int*   lab    = (const int*)  d_in[2];
    const float* conv_w = (const float*)d_in[3];
    const float* conv_b = (const float*)d_in[4];
    const float* bn_g   = (const float*)d_in[5];
    const float* bn_b   = (const float*)d_in[6];
    const float* bn_m   = (const float*)d_in[7];
    const float* bn_v   = (const float*)d_in[8];
    const float* wih    = (const float*)d_in[9];
    const float* whh    = (const float*)d_in[10];
    const float* bih    = (const float*)d_in[11];
    const float* bhh    = (const float*)d_in[12];
    const float* cls_w  = (const float*)d_in[13];
    const float* cls_b  = (const float*)d_in[14];
    const float* crf_s  = (const float*)d_in[15];
    const float* crf_e  = (const float*)d_in[16];
    const float* crf_t  = (const float*)d_in[17];
    float* out = (float*)d_out;

    cudaFuncSetAttribute(k_recur2, cudaFuncAttributeMaxDynamicSharedMemorySize, R2_SMEM);
    cudaFuncSetAttribute(k_gate,   cudaFuncAttributeMaxDynamicSharedMemorySize, GT_SMEM);
    cudaFuncSetAttribute(k_convT,  cudaFuncAttributeMaxDynamicSharedMemorySize, GT_SMEM);

    k_cvt_e <<<B_*T_*E_/256, 256>>>(emb);
    k_cvt_cw<<<C_*KC_/256, 256>>>(conv_w);
    k_cvt_w <<<3*NG*KI/256, 256>>>(wih);
    k_pack_small<<<48, 256>>>(bih, bhh, bn_g, bn_b, bn_m, bn_v, conv_b);

    k_convT<<<dim3(C_/128, M_/128), 256, GT_SMEM>>>();

    for (int l = 0; l < 3; ++l){
        int outpar = (l + 1) & 1;
        int wF32    = (l == 2) ? 1 : 0;
        int wPlanes = (l == 2) ? 0 : 1;
        k_gate<<<dim3(NG/128, M_/128), 256, GT_SMEM>>>(l);
        k_reset<<<128, 256>>>();
        k_recur2<<<64, 256, R2_SMEM>>>(whh, l, outpar, wF32, wPlanes);
    }

    k_cls<<<M_/256, 256>>>(cls_w, cls_b, 1);
    k_crf<<<1, 128>>>(att, lab, crf_s, crf_e, crf_t, out);
}